// round 1
// baseline (speedup 1.0000x reference)
#include <cuda_runtime.h>
#include <math.h>

// Problem constants
#define B_   2
#define CI   16
#define CO   32
#define G_   12
#define R_   12
#define S_   32
#define V_   32768          // 32^3
#define AO   384            // Co*G
#define KG1  192            // Ci*G
#define KG2  384            // Co*G
#define NY   25165824       // B*Co*G*V  (y element count)

// ---------------- scratch (device globals; no allocation allowed) -------------
__device__ float g_bufA[(size_t)B_ * AO * V_];
__device__ float g_bufB[(size_t)B_ * AO * V_];
__device__ float g_bufC[(size_t)B_ * AO * V_];
__device__ float g_w[3 * 144 * R_];          // rbf weights for 3 refs: [ref][(o,g)][r]
__device__ float g_K1[AO * KG1];             // [(a,o)][(c,g)]
__device__ float g_K2[AO * KG2];
__device__ float g_Kres[AO * KG1];
__device__ float g_Krot1[AO * 27];           // [(c,g)][27]
__device__ float g_Krot2[AO * 27];
__device__ float g_acc[320];                 // [0:64) s1 [64:128) q1 [128:192) s2 [192:256) q2 [256:288) bs [288:320) bq
__device__ float g_mu1[64], g_rs1[64], g_mu2[64], g_rs2[64], g_bmu[32], g_brs[32];

// ---------------- small kernels ----------------------------------------------
__global__ void zero_acc_kernel() {
    int t = threadIdx.x;
    if (t < 320) g_acc[t] = 0.f;
}

// rbf weights: w[o,g,r] normalized over r.  H: (G,3,3), Href: (R,3,3)
__global__ void rbf_kernel(const float* __restrict__ H, const float* __restrict__ Href,
                           float* __restrict__ wout) {
    int t = threadIdx.x;              // 144 threads
    if (t >= 144) return;
    int o = t / G_, g = t % G_;
    float M[9];
    #pragma unroll
    for (int i = 0; i < 3; i++)
        #pragma unroll
        for (int k = 0; k < 3; k++) {
            float s = 0.f;
            #pragma unroll
            for (int j = 0; j < 3; j++)
                s += H[o*9 + j*3 + i] * H[g*9 + j*3 + k];
            M[i*3 + k] = s;
        }
    float wv[R_]; float tot = 0.f;
    #pragma unroll
    for (int r = 0; r < R_; r++) {
        float tr = 0.f;
        #pragma unroll
        for (int m = 0; m < 9; m++) tr += M[m] * Href[r*9 + m];
        float c = (tr - 1.f) * 0.5f;
        c = fminf(fmaxf(c, -1.f + 1e-6f), 1.f - 1e-6f);
        float d = acosf(c);
        float ww = expf(-2.f * d * d);   // 2*sigma^2 = 0.5
        wv[r] = ww; tot += ww;
    }
    float inv = 1.f / tot;
    #pragma unroll
    for (int r = 0; r < R_; r++) wout[t * R_ + r] = wv[r] * inv;
}

// K[(a,o),(c,g)] = sum_r Wg[a,c,r] * w[(o,g),r]
__global__ void computeK_kernel(float* __restrict__ dst, const float* __restrict__ Wg,
                                const float* __restrict__ w, int Cin, int total) {
    int stride = gridDim.x * blockDim.x;
    for (int idx = blockIdx.x * blockDim.x + threadIdx.x; idx < total; idx += stride) {
        int cols = Cin * G_;
        int col = idx % cols, row = idx / cols;
        int a = row / G_, o = row % G_;
        int c = col / G_, g = col % G_;
        float s = 0.f;
        #pragma unroll
        for (int r = 0; r < R_; r++)
            s += Wg[(a * Cin + c) * R_ + r] * w[(o * G_ + g) * R_ + r];
        dst[idx] = s;
    }
}

// Rotated 3x3x3 kernels: Krot[(c,g)][v],  v = d*9+h*3+w
__global__ void rotker_kernel(const float* __restrict__ Ws, const float* __restrict__ H,
                              float* __restrict__ Krot) {
    int t = threadIdx.x;
    if (t >= G_ * 27) return;
    int g = t / 27, v = t % 27;
    int d = v / 9, h = (v / 3) % 3, w = v % 3;
    float cz = (float)(d - 1), cy = (float)(h - 1), cx = (float)(w - 1);
    float pix[3];
    #pragma unroll
    for (int j = 0; j < 3; j++)
        pix[j] = cz * H[g*9 + 0*3 + j] + cy * H[g*9 + 1*3 + j] + cx * H[g*9 + 2*3 + j] + 1.0f;
    float tt[3]; int fi[3];
    #pragma unroll
    for (int j = 0; j < 3; j++) {
        float f = floorf(pix[j]);
        tt[j] = pix[j] - f;
        fi[j] = (int)f;
    }
    float wc[8]; int ic[8];
    int n = 0;
    #pragma unroll
    for (int dz = 0; dz < 2; dz++)
        #pragma unroll
        for (int dy = 0; dy < 2; dy++)
            #pragma unroll
            for (int dx = 0; dx < 2; dx++) {
                int iz = fi[0] + dz, iy = fi[1] + dy, ix = fi[2] + dx;
                bool valid = (iz >= 0 && iz <= 2 && iy >= 0 && iy <= 2 && ix >= 0 && ix <= 2);
                float wz = dz ? tt[0] : 1.f - tt[0];
                float wy = dy ? tt[1] : 1.f - tt[1];
                float wx = dx ? tt[2] : 1.f - tt[2];
                int cz_ = min(max(iz, 0), 2), cy_ = min(max(iy, 0), 2), cx_ = min(max(ix, 0), 2);
                ic[n] = cz_*9 + cy_*3 + cx_;
                wc[n] = valid ? (wz * wy * wx) : 0.f;
                n++;
            }
    for (int c = 0; c < CO; c++) {
        float s = 0.f;
        #pragma unroll
        for (int q = 0; q < 8; q++) s += Ws[c*27 + ic[q]] * wc[q];
        Krot[(c * G_ + g) * 27 + v] = s;
    }
}

// ---------------- mix GEMM: C[384,V] = A[384,K] * B[K,V]  per batch ----------
// Optionally fuses relu((b - mu)*rs) on the B load (instance-norm of previous stage)
template <int K, bool FUSE>
__global__ void __launch_bounds__(256) gemm_mix(const float* __restrict__ A,
                                                const float* __restrict__ Bsrc,
                                                float* __restrict__ Cdst,
                                                const float* __restrict__ mu,
                                                const float* __restrict__ rs,
                                                int Cin) {
    int b = blockIdx.z;
    const float* Bb = Bsrc + (size_t)b * K * V_;
    float*       Cb = Cdst + (size_t)b * AO * V_;
    int m0 = blockIdx.y * 128;
    int n0 = blockIdx.x * 128;

    __shared__ float As[16][128];
    __shared__ float Bs[16][128];

    int tid = threadIdx.x;
    int trow = tid >> 4;     // 0..15
    int tcol = tid & 15;     // 0..15
    float acc[8][8];
    #pragma unroll
    for (int i = 0; i < 8; i++)
        #pragma unroll
        for (int j = 0; j < 8; j++) acc[i][j] = 0.f;

    for (int k0 = 0; k0 < K; k0 += 16) {
        // A tile: 128 rows x 16 k = 512 float4 (4 k's per float4)
        #pragma unroll
        for (int i = 0; i < 2; i++) {
            int e = tid + i * 256;      // 0..511
            int m = e >> 2;
            int kq = (e & 3) * 4;
            float4 av = *(const float4*)(A + (size_t)(m0 + m) * K + k0 + kq);
            As[kq + 0][m] = av.x; As[kq + 1][m] = av.y;
            As[kq + 2][m] = av.z; As[kq + 3][m] = av.w;
        }
        // B tile: 16 k x 128 n = 512 float4
        #pragma unroll
        for (int i = 0; i < 2; i++) {
            int e = tid + i * 256;
            int kk = e >> 5;            // 0..15
            int n4 = (e & 31) * 4;
            int kg = k0 + kk;
            float4 bv = *(const float4*)(Bb + (size_t)kg * V_ + n0 + n4);
            if (FUSE) {
                int c = kg / G_;
                float m_ = mu[b * Cin + c], r_ = rs[b * Cin + c];
                bv.x = fmaxf((bv.x - m_) * r_, 0.f);
                bv.y = fmaxf((bv.y - m_) * r_, 0.f);
                bv.z = fmaxf((bv.z - m_) * r_, 0.f);
                bv.w = fmaxf((bv.w - m_) * r_, 0.f);
            }
            *(float4*)(&Bs[kk][n4]) = bv;
        }
        __syncthreads();

        #pragma unroll
        for (int kk = 0; kk < 16; kk++) {
            float a[8], bb[8];
            *(float4*)(a)     = *(const float4*)(&As[kk][trow * 8]);
            *(float4*)(a + 4) = *(const float4*)(&As[kk][trow * 8 + 4]);
            *(float4*)(bb)     = *(const float4*)(&Bs[kk][tcol * 8]);
            *(float4*)(bb + 4) = *(const float4*)(&Bs[kk][tcol * 8 + 4]);
            #pragma unroll
            for (int i = 0; i < 8; i++)
                #pragma unroll
                for (int j = 0; j < 8; j++)
                    acc[i][j] += a[i] * bb[j];
        }
        __syncthreads();
    }
    #pragma unroll
    for (int i = 0; i < 8; i++) {
        float* cp = Cb + (size_t)(m0 + trow * 8 + i) * V_ + n0 + tcol * 8;
        float4 v0 = make_float4(acc[i][0], acc[i][1], acc[i][2], acc[i][3]);
        float4 v1 = make_float4(acc[i][4], acc[i][5], acc[i][6], acc[i][7]);
        *(float4*)(cp)     = v0;
        *(float4*)(cp + 4) = v1;
    }
}

// ---------------- depthwise 3^3 conv (pad=1) + instance-norm partial stats ---
__global__ void __launch_bounds__(256) dwconv_kernel(const float* __restrict__ src,
                                                     const float* __restrict__ Krot,
                                                     float* __restrict__ dst,
                                                     float* __restrict__ accSum,
                                                     float* __restrict__ accSq) {
    int d  = blockIdx.x;     // 0..31
    int ch = blockIdx.y;     // 0..383  (c*G+g)
    int b  = blockIdx.z;
    const float* zin  = src + ((size_t)(b * AO + ch)) * V_;
    float*       zout = dst + ((size_t)(b * AO + ch)) * V_;

    __shared__ float tile[3][34][34];
    __shared__ float kr[27];
    __shared__ float red[256];

    int tid = threadIdx.y * 32 + threadIdx.x;
    if (tid < 27) kr[tid] = Krot[ch * 27 + tid];

    for (int e = tid; e < 3 * 34 * 34; e += 256) {
        int p  = e / 1156;
        int rr = (e % 1156) / 34;
        int cc = e % 34;
        int zp = d - 1 + p, hh = rr - 1, ww = cc - 1;
        float val = 0.f;
        if (zp >= 0 && zp < 32 && hh >= 0 && hh < 32 && ww >= 0 && ww < 32)
            val = zin[zp * 1024 + hh * 32 + ww];
        tile[p][rr][cc] = val;
    }
    __syncthreads();

    float lsum = 0.f, lsq = 0.f;
    int tx = threadIdx.x;
    for (int hh = threadIdx.y; hh < 32; hh += 8) {
        float a = 0.f;
        #pragma unroll
        for (int p = 0; p < 3; p++)
            #pragma unroll
            for (int i = 0; i < 3; i++)
                #pragma unroll
                for (int j = 0; j < 3; j++)
                    a += tile[p][hh + i][tx + j] * kr[p * 9 + i * 3 + j];
        zout[d * 1024 + hh * 32 + tx] = a;
        lsum += a;
        lsq  += a * a;
    }
    // block reduce both quantities
    red[tid] = lsum; __syncthreads();
    for (int s = 128; s > 0; s >>= 1) { if (tid < s) red[tid] += red[tid + s]; __syncthreads(); }
    float bs = red[0]; __syncthreads();
    red[tid] = lsq; __syncthreads();
    for (int s = 128; s > 0; s >>= 1) { if (tid < s) red[tid] += red[tid + s]; __syncthreads(); }
    if (tid == 0) {
        int idx = b * CO + ch / G_;
        atomicAdd(&accSum[idx], bs);
        atomicAdd(&accSq[idx],  red[0]);
    }
}

__global__ void finstat_kernel(const float* __restrict__ sum, const float* __restrict__ sq,
                               float cnt, int n, float* __restrict__ mu, float* __restrict__ rs) {
    int t = threadIdx.x;
    if (t < n) {
        float m = sum[t] / cnt;
        float v = sq[t] / cnt - m * m;
        mu[t] = m;
        rs[t] = rsqrtf(v + 1e-5f);
    }
}

// t = relu((y2 - mu2)*rs2) + res  ; accumulate per-channel batchnorm stats
__global__ void __launch_bounds__(256) combine_kernel() {
    int br  = blockIdx.x;            // b*384 + row
    int b   = br / AO;
    int row = br % AO;
    int a   = row / G_;
    float mu = g_mu2[b * CO + a], rs = g_rs2[b * CO + a];
    const float4* y2 = (const float4*)(g_bufB + (size_t)br * V_);
    const float4* rv = (const float4*)(g_bufC + (size_t)br * V_);
    float4*       tp = (float4*)(g_bufA + (size_t)br * V_);
    __shared__ float red[256];
    int tid = threadIdx.x;
    int base = blockIdx.y * 512 + tid * 2;    // float4 units
    float lsum = 0.f, lsq = 0.f;
    #pragma unroll
    for (int q = 0; q < 2; q++) {
        int i4 = base + q;
        float4 yv = y2[i4];
        float4 rr = rv[i4];
        float4 o;
        o.x = fmaxf((yv.x - mu) * rs, 0.f) + rr.x;
        o.y = fmaxf((yv.y - mu) * rs, 0.f) + rr.y;
        o.z = fmaxf((yv.z - mu) * rs, 0.f) + rr.z;
        o.w = fmaxf((yv.w - mu) * rs, 0.f) + rr.w;
        tp[i4] = o;
        lsum += o.x + o.y + o.z + o.w;
        lsq  += o.x * o.x + o.y * o.y + o.z * o.z + o.w * o.w;
    }
    red[tid] = lsum; __syncthreads();
    for (int s = 128; s > 0; s >>= 1) { if (tid < s) red[tid] += red[tid + s]; __syncthreads(); }
    float bs = red[0]; __syncthreads();
    red[tid] = lsq; __syncthreads();
    for (int s = 128; s > 0; s >>= 1) { if (tid < s) red[tid] += red[tid + s]; __syncthreads(); }
    if (tid == 0) {
        atomicAdd(&g_acc[256 + a], bs);
        atomicAdd(&g_acc[288 + a], red[0]);
    }
}

// out = (t - bmu)*brs*gamma + beta
__global__ void __launch_bounds__(256) final_kernel(float* __restrict__ out,
                                                    const float* __restrict__ gamma,
                                                    const float* __restrict__ beta) {
    int i4 = blockIdx.x * 256 + threadIdx.x;    // 0..6291455
    int row = i4 >> 13;                          // / (V/4)
    int a = (row % AO) / G_;
    float mu = g_bmu[a];
    float sc = g_brs[a] * gamma[a];
    float bt = beta[a];
    float4 t = ((const float4*)g_bufA)[i4];
    float4 o;
    o.x = (t.x - mu) * sc + bt;
    o.y = (t.y - mu) * sc + bt;
    o.z = (t.z - mu) * sc + bt;
    o.w = (t.w - mu) * sc + bt;
    ((float4*)out)[i4] = o;
}

// ---------------- launch ------------------------------------------------------
extern "C" void kernel_launch(void* const* d_in, const int* in_sizes, int n_in,
                              void* d_out, int out_size) {
    const float* x      = (const float*)d_in[0];
    const float* H      = (const float*)d_in[1];
    const float* Href1  = (const float*)d_in[2];
    const float* Href2  = (const float*)d_in[3];
    const float* Hrefr  = (const float*)d_in[4];
    const float* Wg1    = (const float*)d_in[5];
    const float* Ws1    = (const float*)d_in[6];
    const float* Wg2    = (const float*)d_in[7];
    const float* Ws2    = (const float*)d_in[8];
    const float* Wres   = (const float*)d_in[9];
    const float* gamma  = (const float*)d_in[10];
    const float* beta   = (const float*)d_in[11];
    float* out = (float*)d_out;

    float *bufA, *bufB, *bufC, *wbuf, *K1, *K2, *Kres, *Krot1, *Krot2, *acc;
    float *mu1, *rs1, *mu2, *rs2, *bmu, *brs;
    cudaGetSymbolAddress((void**)&bufA,  g_bufA);
    cudaGetSymbolAddress((void**)&bufB,  g_bufB);
    cudaGetSymbolAddress((void**)&bufC,  g_bufC);
    cudaGetSymbolAddress((void**)&wbuf,  g_w);
    cudaGetSymbolAddress((void**)&K1,    g_K1);
    cudaGetSymbolAddress((void**)&K2,    g_K2);
    cudaGetSymbolAddress((void**)&Kres,  g_Kres);
    cudaGetSymbolAddress((void**)&Krot1, g_Krot1);
    cudaGetSymbolAddress((void**)&Krot2, g_Krot2);
    cudaGetSymbolAddress((void**)&acc,   g_acc);
    cudaGetSymbolAddress((void**)&mu1,   g_mu1);
    cudaGetSymbolAddress((void**)&rs1,   g_rs1);
    cudaGetSymbolAddress((void**)&mu2,   g_mu2);
    cudaGetSymbolAddress((void**)&rs2,   g_rs2);
    cudaGetSymbolAddress((void**)&bmu,   g_bmu);
    cudaGetSymbolAddress((void**)&brs,   g_brs);

    zero_acc_kernel<<<1, 320>>>();
    rbf_kernel<<<1, 144>>>(H, Href1, wbuf);
    rbf_kernel<<<1, 144>>>(H, Href2, wbuf + 1728);
    rbf_kernel<<<1, 144>>>(H, Hrefr, wbuf + 2 * 1728);
    computeK_kernel<<<288, 256>>>(K1,   Wg1,  wbuf,            CI, AO * KG1);
    computeK_kernel<<<576, 256>>>(K2,   Wg2,  wbuf + 1728,     CO, AO * KG2);
    computeK_kernel<<<288, 256>>>(Kres, Wres, wbuf + 2 * 1728, CI, AO * KG1);
    rotker_kernel<<<1, 324>>>(Ws1, H, Krot1);
    rotker_kernel<<<1, 324>>>(Ws2, H, Krot2);

    dim3 ggrid(256, 3, 2);
    // z1 = K1 @ x
    gemm_mix<KG1, false><<<ggrid, 256>>>(K1, x, bufA, nullptr, nullptr, 0);
    // y1 = dwconv(z1, Krot1)  + stats
    dwconv_kernel<<<dim3(32, 384, 2), dim3(32, 8)>>>(bufA, Krot1, bufB, acc + 0, acc + 64);
    finstat_kernel<<<1, 64>>>(acc + 0, acc + 64, (float)(G_ * V_), 64, mu1, rs1);
    // z2 = K2 @ relu(instnorm(y1))   (norm fused in B load)
    gemm_mix<KG2, true><<<ggrid, 256>>>(K2, bufB, bufA, mu1, rs1, CO);
    // y2 = dwconv(z2, Krot2) + stats
    dwconv_kernel<<<dim3(32, 384, 2), dim3(32, 8)>>>(bufA, Krot2, bufB, acc + 128, acc + 192);
    finstat_kernel<<<1, 64>>>(acc + 128, acc + 192, (float)(G_ * V_), 64, mu2, rs2);
    // res = Kres @ x
    gemm_mix<KG1, false><<<ggrid, 256>>>(Kres, x, bufC, nullptr, nullptr, 0);
    // t = relu(instnorm(y2)) + res  + batchnorm stats
    combine_kernel<<<dim3(768, 16), 256>>>();
    finstat_kernel<<<1, 32>>>(acc + 256, acc + 288, (float)(B_ * G_ * V_), 32, bmu, brs);
    // out = batchnorm(t)
    final_kernel<<<24576, 256>>>(out, gamma, beta);
    // second output: H passthrough
    cudaMemcpyAsync(out + NY, H, 108 * sizeof(float), cudaMemcpyDeviceToDevice);
}

// round 4
// speedup vs baseline: 1.3406x; 1.3406x over previous
#include <cuda_runtime.h>
#include <cuda_bf16.h>
#include <cstdint>
#include <math.h>

// Problem constants
#define B_   2
#define CI   16
#define CO   32
#define G_   12
#define R_   12
#define S_   32
#define V_   32768          // 32^3
#define AO   384            // Co*G
#define KG1  192            // Ci*G
#define KG2  384            // Co*G
#define NY   25165824       // B*Co*G*V  (y element count)

// ---------------- scratch (device globals; no allocation allowed) -------------
__device__ float g_bufA[(size_t)B_ * AO * V_];
__device__ float g_bufB[(size_t)B_ * AO * V_];
__device__ float g_bufC[(size_t)B_ * AO * V_];
__device__ float g_w[3 * 144 * R_];
__device__ __nv_bfloat16 g_A1h[AO * KG1], g_A1l[AO * KG1];
__device__ __nv_bfloat16 g_A2h[AO * KG2], g_A2l[AO * KG2];
__device__ __nv_bfloat16 g_Arh[AO * KG1], g_Arl[AO * KG1];
__device__ __nv_bfloat16 g_xth[(size_t)B_ * V_ * KG1], g_xtl[(size_t)B_ * V_ * KG1];
__device__ __nv_bfloat16 g_yth[(size_t)B_ * V_ * KG2], g_ytl[(size_t)B_ * V_ * KG2];
__device__ float g_Krot1[AO * 27];
__device__ float g_Krot2[AO * 27];
__device__ float g_acc[320];
__device__ float g_mu1[64], g_rs1[64], g_mu2[64], g_rs2[64], g_bmu[32], g_brs[32];

// ---------------- helpers ------------------------------------------------------
__device__ __forceinline__ uint32_t smem_u32(const void* p) {
    uint32_t a;
    asm("{ .reg .u64 t; cvta.to.shared.u64 t, %1; cvt.u32.u64 %0, t; }" : "=r"(a) : "l"(p));
    return a;
}

#define LDMATRIX_X4(r0, r1, r2, r3, addr) \
    asm volatile("ldmatrix.sync.aligned.m8n8.x4.shared.b16 {%0,%1,%2,%3}, [%4];" \
                 : "=r"(r0), "=r"(r1), "=r"(r2), "=r"(r3) : "r"(addr))
#define LDMATRIX_X2(r0, r1, addr) \
    asm volatile("ldmatrix.sync.aligned.m8n8.x2.shared.b16 {%0,%1}, [%2];" \
                 : "=r"(r0), "=r"(r1) : "r"(addr))
#define MMA_BF16(c0, c1, c2, c3, a0, a1, a2, a3, b0, b1) \
    asm volatile("mma.sync.aligned.m16n8k16.row.col.f32.bf16.bf16.f32 " \
                 "{%0,%1,%2,%3}, {%4,%5,%6,%7}, {%8,%9}, {%0,%1,%2,%3};" \
                 : "+f"(c0), "+f"(c1), "+f"(c2), "+f"(c3) \
                 : "r"(a0), "r"(a1), "r"(a2), "r"(a3), "r"(b0), "r"(b1))

// ---------------- small setup kernels -----------------------------------------
__global__ void zero_acc_kernel() {
    int t = threadIdx.x;
    if (t < 320) g_acc[t] = 0.f;
}

__global__ void rbf_kernel(const float* __restrict__ H, const float* __restrict__ Href,
                           float* __restrict__ wout) {
    int t = threadIdx.x;
    if (t >= 144) return;
    int o = t / G_, g = t % G_;
    float M[9];
    #pragma unroll
    for (int i = 0; i < 3; i++)
        #pragma unroll
        for (int k = 0; k < 3; k++) {
            float s = 0.f;
            #pragma unroll
            for (int j = 0; j < 3; j++)
                s += H[o*9 + j*3 + i] * H[g*9 + j*3 + k];
            M[i*3 + k] = s;
        }
    float wv[R_]; float tot = 0.f;
    #pragma unroll
    for (int r = 0; r < R_; r++) {
        float tr = 0.f;
        #pragma unroll
        for (int m = 0; m < 9; m++) tr += M[m] * Href[r*9 + m];
        float c = (tr - 1.f) * 0.5f;
        c = fminf(fmaxf(c, -1.f + 1e-6f), 1.f - 1e-6f);
        float d = acosf(c);
        float ww = expf(-2.f * d * d);
        wv[r] = ww; tot += ww;
    }
    float inv = 1.f / tot;
    #pragma unroll
    for (int r = 0; r < R_; r++) wout[t * R_ + r] = wv[r] * inv;
}

__global__ void computeK_kernel(__nv_bfloat16* __restrict__ Ah, __nv_bfloat16* __restrict__ Al,
                                const float* __restrict__ Wg, const float* __restrict__ w,
                                int Cin, int total) {
    int stride = gridDim.x * blockDim.x;
    for (int idx = blockIdx.x * blockDim.x + threadIdx.x; idx < total; idx += stride) {
        int cols = Cin * G_;
        int col = idx % cols, row = idx / cols;
        int a = row / G_, o = row % G_;
        int c = col / G_, g = col % G_;
        float s = 0.f;
        #pragma unroll
        for (int r = 0; r < R_; r++)
            s += Wg[(a * Cin + c) * R_ + r] * w[(o * G_ + g) * R_ + r];
        __nv_bfloat16 h = __float2bfloat16(s);
        Ah[idx] = h;
        Al[idx] = __float2bfloat16(s - __bfloat162float(h));
    }
}

__global__ void rotker_kernel(const float* __restrict__ Ws, const float* __restrict__ H,
                              float* __restrict__ Krot) {
    int t = threadIdx.x;
    if (t >= G_ * 27) return;
    int g = t / 27, v = t % 27;
    int d = v / 9, h = (v / 3) % 3, w = v % 3;
    float cz = (float)(d - 1), cy = (float)(h - 1), cx = (float)(w - 1);
    float pix[3];
    #pragma unroll
    for (int j = 0; j < 3; j++)
        pix[j] = cz * H[g*9 + 0*3 + j] + cy * H[g*9 + 1*3 + j] + cx * H[g*9 + 2*3 + j] + 1.0f;
    float tt[3]; int fi[3];
    #pragma unroll
    for (int j = 0; j < 3; j++) {
        float f = floorf(pix[j]);
        tt[j] = pix[j] - f;
        fi[j] = (int)f;
    }
    float wc[8]; int ic[8];
    int n = 0;
    #pragma unroll
    for (int dz = 0; dz < 2; dz++)
        #pragma unroll
        for (int dy = 0; dy < 2; dy++)
            #pragma unroll
            for (int dx = 0; dx < 2; dx++) {
                int iz = fi[0] + dz, iy = fi[1] + dy, ix = fi[2] + dx;
                bool valid = (iz >= 0 && iz <= 2 && iy >= 0 && iy <= 2 && ix >= 0 && ix <= 2);
                float wz = dz ? tt[0] : 1.f - tt[0];
                float wy = dy ? tt[1] : 1.f - tt[1];
                float wx = dx ? tt[2] : 1.f - tt[2];
                int cz_ = min(max(iz, 0), 2), cy_ = min(max(iy, 0), 2), cx_ = min(max(ix, 0), 2);
                ic[n] = cz_*9 + cy_*3 + cx_;
                wc[n] = valid ? (wz * wy * wx) : 0.f;
                n++;
            }
    for (int c = 0; c < CO; c++) {
        float s = 0.f;
        #pragma unroll
        for (int q = 0; q < 8; q++) s += Ws[c*27 + ic[q]] * wc[q];
        Krot[(c * G_ + g) * 27 + v] = s;
    }
}

// ---------------- conversion/transpose passes ---------------------------------
// src [b][K][V] fp32 -> th/tl [b][V][K] bf16 split (optionally fused inst-norm+relu)
template <int K, bool NORM>
__global__ void __launch_bounds__(256) convT_kernel(const float* __restrict__ src,
                                                    __nv_bfloat16* __restrict__ th,
                                                    __nv_bfloat16* __restrict__ tl,
                                                    const float* __restrict__ mu,
                                                    const float* __restrict__ rs) {
    __shared__ float tile[32][33];
    int b = blockIdx.z, k0 = blockIdx.y * 32, n0 = blockIdx.x * 32;
    int tx = threadIdx.x, ty = threadIdx.y;   // 32 x 8
    #pragma unroll
    for (int i = 0; i < 4; i++) {
        int k = ty + i * 8;
        float v = src[((size_t)(b * K + k0 + k)) * V_ + n0 + tx];
        if (NORM) {
            int c = (k0 + k) / G_;
            float m_ = mu[b * CO + c], r_ = rs[b * CO + c];
            v = fmaxf((v - m_) * r_, 0.f);
        }
        tile[k][tx] = v;
    }
    __syncthreads();
    int tid = ty * 32 + tx;
    #pragma unroll
    for (int i = 0; i < 2; i++) {
        int e = tid + i * 256;
        int n = e >> 4, w = e & 15;
        float v0 = tile[2 * w][n], v1 = tile[2 * w + 1][n];
        __nv_bfloat16 h0 = __float2bfloat16(v0), h1 = __float2bfloat16(v1);
        __nv_bfloat16 l0 = __float2bfloat16(v0 - __bfloat162float(h0));
        __nv_bfloat16 l1 = __float2bfloat16(v1 - __bfloat162float(h1));
        size_t base = ((size_t)b * V_ + n0 + n) * K + k0 + 2 * w;
        __nv_bfloat162 hh; hh.x = h0; hh.y = h1;
        __nv_bfloat162 ll; ll.x = l0; ll.y = l1;
        *(__nv_bfloat162*)(th + base) = hh;
        *(__nv_bfloat162*)(tl + base) = ll;
    }
}

// ---------------- mma.sync bf16 GEMM ------------------------------------------
// C[b][384][V] = sum over 3 split terms of A[384][K] @ B[b][V][K]^T
// CTA tile 128x128, warps 2(m) x 4(n) -> warp tile 64x32, K-chunks of 64.
// Double-buffered smem, XOR-swizzled 16B chunks (8 per 128B row).
#define GBUF 32768               // per-stage bytes: 16KB A + 16KB B
#define GSMEM (2 * GBUF)
template <int K>
__global__ void __launch_bounds__(256) gemm_mma(
    const __nv_bfloat16* __restrict__ Ah, const __nv_bfloat16* __restrict__ Al,
    const __nv_bfloat16* __restrict__ Bh, const __nv_bfloat16* __restrict__ Bl,
    float* __restrict__ C) {
    extern __shared__ char smem[];
    uint32_t sbase = smem_u32(smem);

    int tid = threadIdx.x;
    int lane = tid & 31, warp = tid >> 5;
    int wm = warp >> 2;          // 0..1
    int wn = warp & 3;           // 0..3
    int b  = blockIdx.z;
    int m0 = blockIdx.y * 128;
    int n0 = blockIdx.x * 128;

    const __nv_bfloat16* Bhb = Bh + (size_t)b * V_ * K;
    const __nv_bfloat16* Blb = Bl + (size_t)b * V_ * K;
    const int NCHK = K / 64;
    const int NT = 3 * NCHK;

    float acc[4][4][4];
    #pragma unroll
    for (int i = 0; i < 4; i++)
        #pragma unroll
        for (int j = 0; j < 4; j++)
            #pragma unroll
            for (int q = 0; q < 4; q++) acc[i][j][q] = 0.f;

    // per-thread gmem chunk coords (4 chunks of 16B each for A and B)
    uint4 areg[4], breg[4];

    auto ldg = [&](int it) {
        int term = it / NCHK, ch = it % NCHK;
        const __nv_bfloat16* Ap = ((term == 2) ? Al : Ah) + ch * 64;
        const __nv_bfloat16* Bp = ((term == 1) ? Blb : Bhb) + ch * 64;
        #pragma unroll
        for (int i = 0; i < 4; i++) {
            int e = tid + i * 256;
            int r = e >> 3, c = e & 7;
            areg[i] = *(const uint4*)(Ap + (size_t)(m0 + r) * K + c * 8);
            breg[i] = *(const uint4*)(Bp + (size_t)(n0 + r) * K + c * 8);
        }
    };
    auto sts = [&](int buf) {
        char* dst = smem + buf * GBUF;
        #pragma unroll
        for (int i = 0; i < 4; i++) {
            int e = tid + i * 256;
            int r = e >> 3, c = e & 7;
            int off = r * 128 + ((c ^ (r & 7)) << 4);
            *(uint4*)(dst + off) = areg[i];
            *(uint4*)(dst + 16384 + off) = breg[i];
        }
    };

    ldg(0);
    sts(0);
    __syncthreads();

    for (int it = 0; it < NT; it++) {
        int cur = it & 1;
        if (it + 1 < NT) ldg(it + 1);

        uint32_t aBuf = sbase + cur * GBUF;
        uint32_t bBuf = aBuf + 16384;
        #pragma unroll
        for (int kk = 0; kk < 4; kk++) {
            uint32_t af[4][4];
            #pragma unroll
            for (int mt = 0; mt < 4; mt++) {
                int row = wm * 64 + mt * 16 + (lane & 7) + ((lane >> 3) & 1) * 8;
                int cc  = kk * 2 + (lane >> 4);
                uint32_t addr = aBuf + row * 128 + ((cc ^ (row & 7)) << 4);
                LDMATRIX_X4(af[mt][0], af[mt][1], af[mt][2], af[mt][3], addr);
            }
            uint32_t bf[4][2];
            #pragma unroll
            for (int nt = 0; nt < 4; nt++) {
                int l = lane & 15;
                int n = wn * 32 + nt * 8 + (l & 7);
                int cc = kk * 2 + (l >> 3);
                uint32_t addr = bBuf + n * 128 + ((cc ^ (n & 7)) << 4);
                LDMATRIX_X2(bf[nt][0], bf[nt][1], addr);
            }
            #pragma unroll
            for (int mt = 0; mt < 4; mt++)
                #pragma unroll
                for (int nt = 0; nt < 4; nt++)
                    MMA_BF16(acc[mt][nt][0], acc[mt][nt][1], acc[mt][nt][2], acc[mt][nt][3],
                             af[mt][0], af[mt][1], af[mt][2], af[mt][3],
                             bf[nt][0], bf[nt][1]);
        }
        __syncthreads();
        if (it + 1 < NT) {
            sts(cur ^ 1);
            __syncthreads();
        }
    }

    // epilogue: direct float2 stores
    float* Cb = C + (size_t)b * AO * V_;
    int g = lane >> 2, q = lane & 3;
    int mBase = m0 + wm * 64;
    int nBase = n0 + wn * 32;
    #pragma unroll
    for (int mt = 0; mt < 4; mt++) {
        #pragma unroll
        for (int nt = 0; nt < 4; nt++) {
            int row = mBase + mt * 16 + g;
            int col = nBase + nt * 8 + 2 * q;
            float2 v0 = make_float2(acc[mt][nt][0], acc[mt][nt][1]);
            float2 v1 = make_float2(acc[mt][nt][2], acc[mt][nt][3]);
            *(float2*)(Cb + (size_t)row * V_ + col)       = v0;
            *(float2*)(Cb + (size_t)(row + 8) * V_ + col) = v1;
        }
    }
}

// ---------------- depthwise conv + stats --------------------------------------
__global__ void __launch_bounds__(256) dwconv_kernel(const float* __restrict__ src,
                                                     const float* __restrict__ Krot,
                                                     float* __restrict__ dst,
                                                     float* __restrict__ accSum,
                                                     float* __restrict__ accSq) {
    int d  = blockIdx.x;
    int ch = blockIdx.y;
    int b  = blockIdx.z;
    const float* zin  = src + ((size_t)(b * AO + ch)) * V_;
    float*       zout = dst + ((size_t)(b * AO + ch)) * V_;

    __shared__ float tile[3][34][34];
    __shared__ float kr[27];
    __shared__ float red[256];

    int tid = threadIdx.y * 32 + threadIdx.x;
    if (tid < 27) kr[tid] = Krot[ch * 27 + tid];

    for (int e = tid; e < 3 * 34 * 34; e += 256) {
        int p  = e / 1156;
        int rr = (e % 1156) / 34;
        int cc = e % 34;
        int zp = d - 1 + p, hh = rr - 1, ww = cc - 1;
        float val = 0.f;
        if (zp >= 0 && zp < 32 && hh >= 0 && hh < 32 && ww >= 0 && ww < 32)
            val = zin[zp * 1024 + hh * 32 + ww];
        tile[p][rr][cc] = val;
    }
    __syncthreads();

    float lsum = 0.f, lsq = 0.f;
    int tx = threadIdx.x;
    for (int hh = threadIdx.y; hh < 32; hh += 8) {
        float a = 0.f;
        #pragma unroll
        for (int p = 0; p < 3; p++)
            #pragma unroll
            for (int i = 0; i < 3; i++)
                #pragma unroll
                for (int j = 0; j < 3; j++)
                    a += tile[p][hh + i][tx + j] * kr[p * 9 + i * 3 + j];
        zout[d * 1024 + hh * 32 + tx] = a;
        lsum += a;
        lsq  += a * a;
    }
    red[tid] = lsum; __syncthreads();
    for (int s = 128; s > 0; s >>= 1) { if (tid < s) red[tid] += red[tid + s]; __syncthreads(); }
    float bs = red[0]; __syncthreads();
    red[tid] = lsq; __syncthreads();
    for (int s = 128; s > 0; s >>= 1) { if (tid < s) red[tid] += red[tid + s]; __syncthreads(); }
    if (tid == 0) {
        int idx = b * CO + ch / G_;
        atomicAdd(&accSum[idx], bs);
        atomicAdd(&accSq[idx],  red[0]);
    }
}

__global__ void finstat_kernel(const float* __restrict__ sum, const float* __restrict__ sq,
                               float cnt, int n, float* __restrict__ mu, float* __restrict__ rs) {
    int t = threadIdx.x;
    if (t < n) {
        float m = sum[t] / cnt;
        float v = sq[t] / cnt - m * m;
        mu[t] = m;
        rs[t] = rsqrtf(v + 1e-5f);
    }
}

__global__ void __launch_bounds__(256) combine_kernel() {
    int br  = blockIdx.x;
    int b   = br / AO;
    int row = br % AO;
    int a   = row / G_;
    float mu = g_mu2[b * CO + a], rs = g_rs2[b * CO + a];
    const float4* y2 = (const float4*)(g_bufB + (size_t)br * V_);
    const float4* rv = (const float4*)(g_bufC + (size_t)br * V_);
    float4*       tp = (float4*)(g_bufA + (size_t)br * V_);
    __shared__ float red[256];
    int tid = threadIdx.x;
    int base = blockIdx.y * 512 + tid * 2;
    float lsum = 0.f, lsq = 0.f;
    #pragma unroll
    for (int q = 0; q < 2; q++) {
        int i4 = base + q;
        float4 yv = y2[i4];
        float4 rr = rv[i4];
        float4 o;
        o.x = fmaxf((yv.x - mu) * rs, 0.f) + rr.x;
        o.y = fmaxf((yv.y - mu) * rs, 0.f) + rr.y;
        o.z = fmaxf((yv.z - mu) * rs, 0.f) + rr.z;
        o.w = fmaxf((yv.w - mu) * rs, 0.f) + rr.w;
        tp[i4] = o;
        lsum += o.x + o.y + o.z + o.w;
        lsq  += o.x * o.x + o.y * o.y + o.z * o.z + o.w * o.w;
    }
    red[tid] = lsum; __syncthreads();
    for (int s = 128; s > 0; s >>= 1) { if (tid < s) red[tid] += red[tid + s]; __syncthreads(); }
    float bs = red[0]; __syncthreads();
    red[tid] = lsq; __syncthreads();
    for (int s = 128; s > 0; s >>= 1) { if (tid < s) red[tid] += red[tid + s]; __syncthreads(); }
    if (tid == 0) {
        atomicAdd(&g_acc[256 + a], bs);
        atomicAdd(&g_acc[288 + a], red[0]);
    }
}

__global__ void __launch_bounds__(256) final_kernel(float* __restrict__ out,
                                                    const float* __restrict__ gamma,
                                                    const float* __restrict__ beta) {
    int i4 = blockIdx.x * 256 + threadIdx.x;
    int row = i4 >> 13;
    int a = (row % AO) / G_;
    float mu = g_bmu[a];
    float sc = g_brs[a] * gamma[a];
    float bt = beta[a];
    float4 t = ((const float4*)g_bufA)[i4];
    float4 o;
    o.x = (t.x - mu) * sc + bt;
    o.y = (t.y - mu) * sc + bt;
    o.z = (t.z - mu) * sc + bt;
    o.w = (t.w - mu) * sc + bt;
    ((float4*)out)[i4] = o;
}

// ---------------- launch ------------------------------------------------------
extern "C" void kernel_launch(void* const* d_in, const int* in_sizes, int n_in,
                              void* d_out, int out_size) {
    const float* x      = (const float*)d_in[0];
    const float* H      = (const float*)d_in[1];
    const float* Href1  = (const float*)d_in[2];
    const float* Href2  = (const float*)d_in[3];
    const float* Hrefr  = (const float*)d_in[4];
    const float* Wg1    = (const float*)d_in[5];
    const float* Ws1    = (const float*)d_in[6];
    const float* Wg2    = (const float*)d_in[7];
    const float* Ws2    = (const float*)d_in[8];
    const float* Wres   = (const float*)d_in[9];
    const float* gamma  = (const float*)d_in[10];
    const float* beta   = (const float*)d_in[11];
    float* out = (float*)d_out;

    float *bufA, *bufB, *bufC, *wbuf, *Krot1, *Krot2, *acc;
    float *mu1, *rs1, *mu2, *rs2, *bmu, *brs;
    __nv_bfloat16 *A1h, *A1l, *A2h, *A2l, *Arh, *Arl, *xth, *xtl, *yth, *ytl;
    cudaGetSymbolAddress((void**)&bufA,  g_bufA);
    cudaGetSymbolAddress((void**)&bufB,  g_bufB);
    cudaGetSymbolAddress((void**)&bufC,  g_bufC);
    cudaGetSymbolAddress((void**)&wbuf,  g_w);
    cudaGetSymbolAddress((void**)&A1h,   g_A1h);
    cudaGetSymbolAddress((void**)&A1l,   g_A1l);
    cudaGetSymbolAddress((void**)&A2h,   g_A2h);
    cudaGetSymbolAddress((void**)&A2l,   g_A2l);
    cudaGetSymbolAddress((void**)&Arh,   g_Arh);
    cudaGetSymbolAddress((void**)&Arl,   g_Arl);
    cudaGetSymbolAddress((void**)&xth,   g_xth);
    cudaGetSymbolAddress((void**)&xtl,   g_xtl);
    cudaGetSymbolAddress((void**)&yth,   g_yth);
    cudaGetSymbolAddress((void**)&ytl,   g_ytl);
    cudaGetSymbolAddress((void**)&Krot1, g_Krot1);
    cudaGetSymbolAddress((void**)&Krot2, g_Krot2);
    cudaGetSymbolAddress((void**)&acc,   g_acc);
    cudaGetSymbolAddress((void**)&mu1,   g_mu1);
    cudaGetSymbolAddress((void**)&rs1,   g_rs1);
    cudaGetSymbolAddress((void**)&mu2,   g_mu2);
    cudaGetSymbolAddress((void**)&rs2,   g_rs2);
    cudaGetSymbolAddress((void**)&bmu,   g_bmu);
    cudaGetSymbolAddress((void**)&brs,   g_brs);

    cudaFuncSetAttribute(gemm_mma<KG1>, cudaFuncAttributeMaxDynamicSharedMemorySize, GSMEM);
    cudaFuncSetAttribute(gemm_mma<KG2>, cudaFuncAttributeMaxDynamicSharedMemorySize, GSMEM);

    zero_acc_kernel<<<1, 320>>>();
    rbf_kernel<<<1, 144>>>(H, Href1, wbuf);
    rbf_kernel<<<1, 144>>>(H, Href2, wbuf + 1728);
    rbf_kernel<<<1, 144>>>(H, Hrefr, wbuf + 2 * 1728);
    computeK_kernel<<<288, 256>>>(A1h, A1l, Wg1,  wbuf,            CI, AO * KG1);
    computeK_kernel<<<576, 256>>>(A2h, A2l, Wg2,  wbuf + 1728,     CO, AO * KG2);
    computeK_kernel<<<288, 256>>>(Arh, Arl, Wres, wbuf + 2 * 1728, CI, AO * KG1);
    rotker_kernel<<<1, 324>>>(Ws1, H, Krot1);
    rotker_kernel<<<1, 324>>>(Ws2, H, Krot2);

    // x -> split-bf16 transposed [b][n][k]
    convT_kernel<KG1, false><<<dim3(1024, 6, 2), dim3(32, 8)>>>(x, xth, xtl, nullptr, nullptr);

    dim3 ggrid(256, 3, 2);
    // z1 = K1 @ x
    gemm_mma<KG1><<<ggrid, 256, GSMEM>>>(A1h, A1l, xth, xtl, bufA);
    // y1 = dwconv(z1) + stats
    dwconv_kernel<<<dim3(32, 384, 2), dim3(32, 8)>>>(bufA, Krot1, bufB, acc + 0, acc + 64);
    finstat_kernel<<<1, 64>>>(acc + 0, acc + 64, (float)(G_ * V_), 64, mu1, rs1);
    // relu(instnorm(y1)) -> split-bf16 transposed
    convT_kernel<KG2, true><<<dim3(1024, 12, 2), dim3(32, 8)>>>(bufB, yth, ytl, mu1, rs1);
    // z2 = K2 @ (.)
    gemm_mma<KG2><<<ggrid, 256, GSMEM>>>(A2h, A2l, yth, ytl, bufA);
    // y2 = dwconv(z2) + stats
    dwconv_kernel<<<dim3(32, 384, 2), dim3(32, 8)>>>(bufA, Krot2, bufB, acc + 128, acc + 192);
    finstat_kernel<<<1, 64>>>(acc + 128, acc + 192, (float)(G_ * V_), 64, mu2, rs2);
    // res = Kres @ x
    gemm_mma<KG1><<<ggrid, 256, GSMEM>>>(Arh, Arl, xth, xtl, bufC);
    // t = relu(instnorm(y2)) + res, + bn stats
    combine_kernel<<<dim3(768, 16), 256>>>();
    finstat_kernel<<<1, 32>>>(acc + 256, acc + 288, (float)(B_ * G_ * V_), 32, bmu, brs);
    // out = batchnorm(t)
    final_kernel<<<24576, 256>>>(out, gamma, beta);
    cudaMemcpyAsync(out + NY, H, 108 * sizeof(float), cudaMemcpyDeviceToDevice);
}

// round 5
// speedup vs baseline: 2.3650x; 1.7641x over previous
#include <cuda_runtime.h>
#include <cuda_fp16.h>
#include <cstdint>
#include <math.h>

// Problem constants
#define B_   2
#define CI   16
#define CO   32
#define G_   12
#define R_   12
#define S_   32
#define V_   32768          // 32^3
#define AO   384            // Co*G
#define KG1  192            // Ci*G
#define KG2  384            // Co*G
#define NY   25165824       // B*Co*G*V  (y element count)

// ---------------- scratch (device globals; no allocation allowed) -------------
__device__ float g_bufA[(size_t)B_ * AO * V_];
__device__ float g_bufB[(size_t)B_ * AO * V_];
__device__ float g_bufC[(size_t)B_ * AO * V_];
__device__ float g_w[3 * 144 * R_];
__device__ __half g_Acmb1[2 * AO * KG1];     // [K1 ; Kres]  (768 x 192)
__device__ __half g_A2[AO * KG2];            // 384 x 384
__device__ __half g_xt[(size_t)B_ * V_ * KG1];   // x transposed fp16 [b][v][k]
__device__ __half g_yt[(size_t)B_ * V_ * KG2];   // norm(relu(y1)) transposed fp16
__device__ float g_Krot1[AO * 27];
__device__ float g_Krot2[AO * 27];
__device__ float g_acc[320];
__device__ float g_mu1[64], g_rs1[64], g_mu2[64], g_rs2[64], g_bmu[32], g_brs[32];

// ---------------- helpers ------------------------------------------------------
__device__ __forceinline__ uint32_t smem_u32(const void* p) {
    uint32_t a;
    asm("{ .reg .u64 t; cvta.to.shared.u64 t, %1; cvt.u32.u64 %0, t; }" : "=r"(a) : "l"(p));
    return a;
}

#define LDMATRIX_X4(r0, r1, r2, r3, addr) \
    asm volatile("ldmatrix.sync.aligned.m8n8.x4.shared.b16 {%0,%1,%2,%3}, [%4];" \
                 : "=r"(r0), "=r"(r1), "=r"(r2), "=r"(r3) : "r"(addr))
#define LDMATRIX_X2(r0, r1, addr) \
    asm volatile("ldmatrix.sync.aligned.m8n8.x2.shared.b16 {%0,%1}, [%2];" \
                 : "=r"(r0), "=r"(r1) : "r"(addr))
#define MMA_F16(c0, c1, c2, c3, a0, a1, a2, a3, b0, b1) \
    asm volatile("mma.sync.aligned.m16n8k16.row.col.f32.f16.f16.f32 " \
                 "{%0,%1,%2,%3}, {%4,%5,%6,%7}, {%8,%9}, {%0,%1,%2,%3};" \
                 : "+f"(c0), "+f"(c1), "+f"(c2), "+f"(c3) \
                 : "r"(a0), "r"(a1), "r"(a2), "r"(a3), "r"(b0), "r"(b1))

// ---------------- small setup kernels -----------------------------------------
__global__ void zero_acc_kernel() {
    int t = threadIdx.x;
    if (t < 320) g_acc[t] = 0.f;
}

__global__ void rbf_kernel(const float* __restrict__ H, const float* __restrict__ Href,
                           float* __restrict__ wout) {
    int t = threadIdx.x;
    if (t >= 144) return;
    int o = t / G_, g = t % G_;
    float M[9];
    #pragma unroll
    for (int i = 0; i < 3; i++)
        #pragma unroll
        for (int k = 0; k < 3; k++) {
            float s = 0.f;
            #pragma unroll
            for (int j = 0; j < 3; j++)
                s += H[o*9 + j*3 + i] * H[g*9 + j*3 + k];
            M[i*3 + k] = s;
        }
    float wv[R_]; float tot = 0.f;
    #pragma unroll
    for (int r = 0; r < R_; r++) {
        float tr = 0.f;
        #pragma unroll
        for (int m = 0; m < 9; m++) tr += M[m] * Href[r*9 + m];
        float c = (tr - 1.f) * 0.5f;
        c = fminf(fmaxf(c, -1.f + 1e-6f), 1.f - 1e-6f);
        float d = acosf(c);
        float ww = expf(-2.f * d * d);
        wv[r] = ww; tot += ww;
    }
    float inv = 1.f / tot;
    #pragma unroll
    for (int r = 0; r < R_; r++) wout[t * R_ + r] = wv[r] * inv;
}

__global__ void computeK_kernel(__half* __restrict__ Ah,
                                const float* __restrict__ Wg, const float* __restrict__ w,
                                int Cin, int total) {
    int stride = gridDim.x * blockDim.x;
    for (int idx = blockIdx.x * blockDim.x + threadIdx.x; idx < total; idx += stride) {
        int cols = Cin * G_;
        int col = idx % cols, row = idx / cols;
        int a = row / G_, o = row % G_;
        int c = col / G_, g = col % G_;
        float s = 0.f;
        #pragma unroll
        for (int r = 0; r < R_; r++)
            s += Wg[(a * Cin + c) * R_ + r] * w[(o * G_ + g) * R_ + r];
        Ah[idx] = __float2half_rn(s);
    }
}

__global__ void rotker_kernel(const float* __restrict__ Ws, const float* __restrict__ H,
                              float* __restrict__ Krot) {
    int t = threadIdx.x;
    if (t >= G_ * 27) return;
    int g = t / 27, v = t % 27;
    int d = v / 9, h = (v / 3) % 3, w = v % 3;
    float cz = (float)(d - 1), cy = (float)(h - 1), cx = (float)(w - 1);
    float pix[3];
    #pragma unroll
    for (int j = 0; j < 3; j++)
        pix[j] = cz * H[g*9 + 0*3 + j] + cy * H[g*9 + 1*3 + j] + cx * H[g*9 + 2*3 + j] + 1.0f;
    float tt[3]; int fi[3];
    #pragma unroll
    for (int j = 0; j < 3; j++) {
        float f = floorf(pix[j]);
        tt[j] = pix[j] - f;
        fi[j] = (int)f;
    }
    float wc[8]; int ic[8];
    int n = 0;
    #pragma unroll
    for (int dz = 0; dz < 2; dz++)
        #pragma unroll
        for (int dy = 0; dy < 2; dy++)
            #pragma unroll
            for (int dx = 0; dx < 2; dx++) {
                int iz = fi[0] + dz, iy = fi[1] + dy, ix = fi[2] + dx;
                bool valid = (iz >= 0 && iz <= 2 && iy >= 0 && iy <= 2 && ix >= 0 && ix <= 2);
                float wz = dz ? tt[0] : 1.f - tt[0];
                float wy = dy ? tt[1] : 1.f - tt[1];
                float wx = dx ? tt[2] : 1.f - tt[2];
                int cz_ = min(max(iz, 0), 2), cy_ = min(max(iy, 0), 2), cx_ = min(max(ix, 0), 2);
                ic[n] = cz_*9 + cy_*3 + cx_;
                wc[n] = valid ? (wz * wy * wx) : 0.f;
                n++;
            }
    for (int c = 0; c < CO; c++) {
        float s = 0.f;
        #pragma unroll
        for (int q = 0; q < 8; q++) s += Ws[c*27 + ic[q]] * wc[q];
        Krot[(c * G_ + g) * 27 + v] = s;
    }
}

// ---------------- conversion/transpose pass ------------------------------------
// src [b][K][V] fp32 -> t [b][V][K] fp16 (optionally fused inst-norm + relu)
template <int K, bool NORM>
__global__ void __launch_bounds__(256) convT_kernel(const float* __restrict__ src,
                                                    __half* __restrict__ th,
                                                    const float* __restrict__ mu,
                                                    const float* __restrict__ rs) {
    __shared__ float tile[32][33];
    int b = blockIdx.z, k0 = blockIdx.y * 32, n0 = blockIdx.x * 32;
    int tx = threadIdx.x, ty = threadIdx.y;   // 32 x 8
    #pragma unroll
    for (int i = 0; i < 4; i++) {
        int k = ty + i * 8;
        float v = src[((size_t)(b * K + k0 + k)) * V_ + n0 + tx];
        if (NORM) {
            int c = (k0 + k) / G_;
            float m_ = mu[b * CO + c], r_ = rs[b * CO + c];
            v = fmaxf((v - m_) * r_, 0.f);
        }
        tile[k][tx] = v;
    }
    __syncthreads();
    int tid = ty * 32 + tx;
    #pragma unroll
    for (int i = 0; i < 2; i++) {
        int e = tid + i * 256;
        int n = e >> 4, w = e & 15;
        float v0 = tile[2 * w][n], v1 = tile[2 * w + 1][n];
        __half2 hh;
        hh.x = __float2half_rn(v0);
        hh.y = __float2half_rn(v1);
        size_t base = ((size_t)b * V_ + n0 + n) * K + k0 + 2 * w;
        *(__half2*)(th + base) = hh;
    }
}

// ---------------- mma.sync fp16 GEMM ------------------------------------------
// C[b][Mtot][V] = A[Mtot][K] @ B[b][V][K]^T   (Mtot = 128*gridDim.y)
// Rows >= 384 go to C1 (residual), rows < 384 to C0.
// CTA tile 128x128, warps 2(m) x 4(n), K-chunks of 64, double-buffered smem.
#define GBUF 32768               // per-stage bytes: 16KB A + 16KB B
#define GSMEM (2 * GBUF)
template <int K>
__global__ void __launch_bounds__(256) gemm_h(
    const __half* __restrict__ A, const __half* __restrict__ B,
    float* __restrict__ C0, float* __restrict__ C1) {
    extern __shared__ char smem[];
    uint32_t sbase = smem_u32(smem);

    int tid = threadIdx.x;
    int lane = tid & 31, warp = tid >> 5;
    int wm = warp >> 2;          // 0..1
    int wn = warp & 3;           // 0..3
    int b  = blockIdx.z;
    int m0 = blockIdx.y * 128;
    int n0 = blockIdx.x * 128;

    const __half* Bb = B + (size_t)b * V_ * K;
    const int NT = K / 64;

    float acc[4][4][4];
    #pragma unroll
    for (int i = 0; i < 4; i++)
        #pragma unroll
        for (int j = 0; j < 4; j++)
            #pragma unroll
            for (int q = 0; q < 4; q++) acc[i][j][q] = 0.f;

    uint4 areg[4], breg[4];

    auto ldg = [&](int ch) {
        const __half* Ap = A + ch * 64;
        const __half* Bp = Bb + ch * 64;
        #pragma unroll
        for (int i = 0; i < 4; i++) {
            int e = tid + i * 256;
            int r = e >> 3, c = e & 7;
            areg[i] = *(const uint4*)(Ap + (size_t)(m0 + r) * K + c * 8);
            breg[i] = *(const uint4*)(Bp + (size_t)(n0 + r) * K + c * 8);
        }
    };
    auto sts = [&](int buf) {
        char* dst = smem + buf * GBUF;
        #pragma unroll
        for (int i = 0; i < 4; i++) {
            int e = tid + i * 256;
            int r = e >> 3, c = e & 7;
            int off = r * 128 + ((c ^ (r & 7)) << 4);
            *(uint4*)(dst + off) = areg[i];
            *(uint4*)(dst + 16384 + off) = breg[i];
        }
    };

    ldg(0);
    sts(0);
    __syncthreads();

    for (int it = 0; it < NT; it++) {
        int cur = it & 1;
        if (it + 1 < NT) ldg(it + 1);

        uint32_t aBuf = sbase + cur * GBUF;
        uint32_t bBuf = aBuf + 16384;
        #pragma unroll
        for (int kk = 0; kk < 4; kk++) {
            uint32_t af[4][4];
            #pragma unroll
            for (int mt = 0; mt < 4; mt++) {
                int row = wm * 64 + mt * 16 + (lane & 7) + ((lane >> 3) & 1) * 8;
                int cc  = kk * 2 + (lane >> 4);
                uint32_t addr = aBuf + row * 128 + ((cc ^ (row & 7)) << 4);
                LDMATRIX_X4(af[mt][0], af[mt][1], af[mt][2], af[mt][3], addr);
            }
            uint32_t bf[4][2];
            #pragma unroll
            for (int nt = 0; nt < 4; nt++) {
                int l = lane & 15;
                int n = wn * 32 + nt * 8 + (l & 7);
                int cc = kk * 2 + (l >> 3);
                uint32_t addr = bBuf + n * 128 + ((cc ^ (n & 7)) << 4);
                LDMATRIX_X2(bf[nt][0], bf[nt][1], addr);
            }
            #pragma unroll
            for (int mt = 0; mt < 4; mt++)
                #pragma unroll
                for (int nt = 0; nt < 4; nt++)
                    MMA_F16(acc[mt][nt][0], acc[mt][nt][1], acc[mt][nt][2], acc[mt][nt][3],
                            af[mt][0], af[mt][1], af[mt][2], af[mt][3],
                            bf[nt][0], bf[nt][1]);
        }
        __syncthreads();
        if (it + 1 < NT) {
            sts(cur ^ 1);
            __syncthreads();
        }
    }

    // epilogue
    float* Cb;
    int mloc;
    if (m0 < AO) { Cb = C0 + (size_t)b * AO * V_; mloc = m0; }
    else         { Cb = C1 + (size_t)b * AO * V_; mloc = m0 - AO; }
    int g = lane >> 2, q = lane & 3;
    int mBase = mloc + wm * 64;
    int nBase = n0 + wn * 32;
    #pragma unroll
    for (int mt = 0; mt < 4; mt++) {
        #pragma unroll
        for (int nt = 0; nt < 4; nt++) {
            int row = mBase + mt * 16 + g;
            int col = nBase + nt * 8 + 2 * q;
            float2 v0 = make_float2(acc[mt][nt][0], acc[mt][nt][1]);
            float2 v1 = make_float2(acc[mt][nt][2], acc[mt][nt][3]);
            *(float2*)(Cb + (size_t)row * V_ + col)       = v0;
            *(float2*)(Cb + (size_t)(row + 8) * V_ + col) = v1;
        }
    }
}

// ---------------- depthwise conv (8 output planes/CTA) + stats ----------------
__global__ void __launch_bounds__(256) dwconv_kernel(const float* __restrict__ src,
                                                     const float* __restrict__ Krot,
                                                     float* __restrict__ dst,
                                                     float* __restrict__ accSum,
                                                     float* __restrict__ accSq) {
    int dg = blockIdx.x;     // 0..3 (8 planes each)
    int ch = blockIdx.y;     // 0..383
    int b  = blockIdx.z;
    const float* zin  = src + ((size_t)(b * AO + ch)) * V_;
    float*       zout = dst + ((size_t)(b * AO + ch)) * V_;

    __shared__ float tile[10][34][34];
    __shared__ float kr[27];
    __shared__ float red[256];

    int tid = threadIdx.x;
    if (tid < 27) kr[tid] = Krot[ch * 27 + tid];

    int z0 = dg * 8;
    for (int e = tid; e < 10 * 1156; e += 256) {
        int p  = e / 1156;
        int rr = (e % 1156) / 34;
        int cc = e % 34;
        int zp = z0 - 1 + p, hh = rr - 1, ww = cc - 1;
        float val = 0.f;
        if (zp >= 0 && zp < 32 && hh >= 0 && hh < 32 && ww >= 0 && ww < 32)
            val = zin[zp * 1024 + hh * 32 + ww];
        tile[p][rr][cc] = val;
    }
    __syncthreads();

    float krr[27];
    #pragma unroll
    for (int m = 0; m < 27; m++) krr[m] = kr[m];

    float lsum = 0.f, lsq = 0.f;
    int tx = tid & 31, ty = tid >> 5;   // 32 x 8
    #pragma unroll
    for (int od = 0; od < 8; od++) {
        for (int hh = ty; hh < 32; hh += 8) {
            float a = 0.f;
            #pragma unroll
            for (int p = 0; p < 3; p++)
                #pragma unroll
                for (int i = 0; i < 3; i++)
                    #pragma unroll
                    for (int j = 0; j < 3; j++)
                        a += tile[od + p][hh + i][tx + j] * krr[p * 9 + i * 3 + j];
            zout[(z0 + od) * 1024 + hh * 32 + tx] = a;
            lsum += a;
            lsq  += a * a;
        }
    }
    red[tid] = lsum; __syncthreads();
    for (int s = 128; s > 0; s >>= 1) { if (tid < s) red[tid] += red[tid + s]; __syncthreads(); }
    float bs = red[0]; __syncthreads();
    red[tid] = lsq; __syncthreads();
    for (int s = 128; s > 0; s >>= 1) { if (tid < s) red[tid] += red[tid + s]; __syncthreads(); }
    if (tid == 0) {
        int idx = b * CO + ch / G_;
        atomicAdd(&accSum[idx], bs);
        atomicAdd(&accSq[idx],  red[0]);
    }
}

__global__ void finstat_kernel(const float* __restrict__ sum, const float* __restrict__ sq,
                               float cnt, int n, float* __restrict__ mu, float* __restrict__ rs) {
    int t = threadIdx.x;
    if (t < n) {
        float m = sum[t] / cnt;
        float v = sq[t] / cnt - m * m;
        mu[t] = m;
        rs[t] = rsqrtf(v + 1e-5f);
    }
}

__global__ void __launch_bounds__(256) combine_kernel() {
    int br  = blockIdx.x;
    int b   = br / AO;
    int row = br % AO;
    int a   = row / G_;
    float mu = g_mu2[b * CO + a], rs = g_rs2[b * CO + a];
    const float4* y2 = (const float4*)(g_bufB + (size_t)br * V_);
    const float4* rv = (const float4*)(g_bufC + (size_t)br * V_);
    float4*       tp = (float4*)(g_bufA + (size_t)br * V_);
    __shared__ float red[256];
    int tid = threadIdx.x;
    int base = blockIdx.y * 512 + tid * 2;
    float lsum = 0.f, lsq = 0.f;
    #pragma unroll
    for (int q = 0; q < 2; q++) {
        int i4 = base + q;
        float4 yv = y2[i4];
        float4 rr = rv[i4];
        float4 o;
        o.x = fmaxf((yv.x - mu) * rs, 0.f) + rr.x;
        o.y = fmaxf((yv.y - mu) * rs, 0.f) + rr.y;
        o.z = fmaxf((yv.z - mu) * rs, 0.f) + rr.z;
        o.w = fmaxf((yv.w - mu) * rs, 0.f) + rr.w;
        tp[i4] = o;
        lsum += o.x + o.y + o.z + o.w;
        lsq  += o.x * o.x + o.y * o.y + o.z * o.z + o.w * o.w;
    }
    red[tid] = lsum; __syncthreads();
    for (int s = 128; s > 0; s >>= 1) { if (tid < s) red[tid] += red[tid + s]; __syncthreads(); }
    float bs = red[0]; __syncthreads();
    red[tid] = lsq; __syncthreads();
    for (int s = 128; s > 0; s >>= 1) { if (tid < s) red[tid] += red[tid + s]; __syncthreads(); }
    if (tid == 0) {
        atomicAdd(&g_acc[256 + a], bs);
        atomicAdd(&g_acc[288 + a], red[0]);
    }
}

__global__ void __launch_bounds__(256) final_kernel(float* __restrict__ out,
                                                    const float* __restrict__ gamma,
                                                    const float* __restrict__ beta) {
    int i4 = blockIdx.x * 256 + threadIdx.x;
    int row = i4 >> 13;
    int a = (row % AO) / G_;
    float mu = g_bmu[a];
    float sc = g_brs[a] * gamma[a];
    float bt = beta[a];
    float4 t = ((const float4*)g_bufA)[i4];
    float4 o;
    o.x = (t.x - mu) * sc + bt;
    o.y = (t.y - mu) * sc + bt;
    o.z = (t.z - mu) * sc + bt;
    o.w = (t.w - mu) * sc + bt;
    ((float4*)out)[i4] = o;
}

// ---------------- launch ------------------------------------------------------
extern "C" void kernel_launch(void* const* d_in, const int* in_sizes, int n_in,
                              void* d_out, int out_size) {
    const float* x      = (const float*)d_in[0];
    const float* H      = (const float*)d_in[1];
    const float* Href1  = (const float*)d_in[2];
    const float* Href2  = (const float*)d_in[3];
    const float* Hrefr  = (const float*)d_in[4];
    const float* Wg1    = (const float*)d_in[5];
    const float* Ws1    = (const float*)d_in[6];
    const float* Wg2    = (const float*)d_in[7];
    const float* Ws2    = (const float*)d_in[8];
    const float* Wres   = (const float*)d_in[9];
    const float* gamma  = (const float*)d_in[10];
    const float* beta   = (const float*)d_in[11];
    float* out = (float*)d_out;

    float *bufA, *bufB, *bufC, *wbuf, *Krot1, *Krot2, *acc;
    float *mu1, *rs1, *mu2, *rs2, *bmu, *brs;
    __half *Acmb1, *A2, *xt, *yt;
    cudaGetSymbolAddress((void**)&bufA,  g_bufA);
    cudaGetSymbolAddress((void**)&bufB,  g_bufB);
    cudaGetSymbolAddress((void**)&bufC,  g_bufC);
    cudaGetSymbolAddress((void**)&wbuf,  g_w);
    cudaGetSymbolAddress((void**)&Acmb1, g_Acmb1);
    cudaGetSymbolAddress((void**)&A2,    g_A2);
    cudaGetSymbolAddress((void**)&xt,    g_xt);
    cudaGetSymbolAddress((void**)&yt,    g_yt);
    cudaGetSymbolAddress((void**)&Krot1, g_Krot1);
    cudaGetSymbolAddress((void**)&Krot2, g_Krot2);
    cudaGetSymbolAddress((void**)&acc,   g_acc);
    cudaGetSymbolAddress((void**)&mu1,   g_mu1);
    cudaGetSymbolAddress((void**)&rs1,   g_rs1);
    cudaGetSymbolAddress((void**)&mu2,   g_mu2);
    cudaGetSymbolAddress((void**)&rs2,   g_rs2);
    cudaGetSymbolAddress((void**)&bmu,   g_bmu);
    cudaGetSymbolAddress((void**)&brs,   g_brs);

    cudaFuncSetAttribute(gemm_h<KG1>, cudaFuncAttributeMaxDynamicSharedMemorySize, GSMEM);
    cudaFuncSetAttribute(gemm_h<KG2>, cudaFuncAttributeMaxDynamicSharedMemorySize, GSMEM);

    zero_acc_kernel<<<1, 320>>>();
    rbf_kernel<<<1, 144>>>(H, Href1, wbuf);
    rbf_kernel<<<1, 144>>>(H, Href2, wbuf + 1728);
    rbf_kernel<<<1, 144>>>(H, Hrefr, wbuf + 2 * 1728);
    computeK_kernel<<<288, 256>>>(Acmb1,            Wg1,  wbuf,            CI, AO * KG1);
    computeK_kernel<<<576, 256>>>(A2,               Wg2,  wbuf + 1728,     CO, AO * KG2);
    computeK_kernel<<<288, 256>>>(Acmb1 + AO * KG1, Wres, wbuf + 2 * 1728, CI, AO * KG1);
    rotker_kernel<<<1, 324>>>(Ws1, H, Krot1);
    rotker_kernel<<<1, 324>>>(Ws2, H, Krot2);

    // x -> fp16 transposed [b][v][k]
    convT_kernel<KG1, false><<<dim3(1024, 6, 2), dim3(32, 8)>>>(x, xt, nullptr, nullptr);

    // fused: [z1 ; res] = [K1 ; Kres] @ x   (M = 768)
    gemm_h<KG1><<<dim3(256, 6, 2), 256, GSMEM>>>(Acmb1, xt, bufA, bufC);
    // y1 = dwconv(z1) + stats
    dwconv_kernel<<<dim3(4, 384, 2), 256>>>(bufA, Krot1, bufB, acc + 0, acc + 64);
    finstat_kernel<<<1, 64>>>(acc + 0, acc + 64, (float)(G_ * V_), 64, mu1, rs1);
    // relu(instnorm(y1)) -> fp16 transposed
    convT_kernel<KG2, true><<<dim3(1024, 12, 2), dim3(32, 8)>>>(bufB, yt, mu1, rs1);
    // z2 = K2 @ (.)
    gemm_h<KG2><<<dim3(256, 3, 2), 256, GSMEM>>>(A2, yt, bufA, bufA);
    // y2 = dwconv(z2) + stats
    dwconv_kernel<<<dim3(4, 384, 2), 256>>>(bufA, Krot2, bufB, acc + 128, acc + 192);
    finstat_kernel<<<1, 64>>>(acc + 128, acc + 192, (float)(G_ * V_), 64, mu2, rs2);
    // t = relu(instnorm(y2)) + res, + bn stats
    combine_kernel<<<dim3(768, 16), 256>>>();
    finstat_kernel<<<1, 32>>>(acc + 256, acc + 288, (float)(B_ * G_ * V_), 32, bmu, brs);
    // out = batchnorm(t)
    final_kernel<<<24576, 256>>>(out, gamma, beta);
    cudaMemcpyAsync(out + NY, H, 108 * sizeof(float), cudaMemcpyDeviceToDevice);
}

// round 6
// speedup vs baseline: 2.4754x; 1.0467x over previous
#include <cuda_runtime.h>
#include <cuda_fp16.h>
#include <cstdint>
#include <math.h>

// Problem constants
#define B_   2
#define CI   16
#define CO   32
#define G_   12
#define R_   12
#define S_   32
#define V_   32768          // 32^3
#define AO   384            // Co*G
#define KG1  192            // Ci*G
#define KG2  384            // Co*G
#define NY   25165824       // B*Co*G*V  (y element count)

// ---------------- scratch (device globals; no allocation allowed) -------------
__device__ float g_bufA[(size_t)B_ * AO * V_];
__device__ float g_bufB[(size_t)B_ * AO * V_];
__device__ float g_bufC[(size_t)B_ * AO * V_];
__device__ float g_w[3 * 144 * R_];
__device__ __half g_Acmb1[2 * AO * KG1];     // [K1 ; Kres]  (768 x 192)
__device__ __half g_A2[AO * KG2];            // 384 x 384
__device__ __half g_xt[(size_t)B_ * V_ * KG1];   // x transposed fp16 [b][v][k]
__device__ __half g_yt[(size_t)B_ * V_ * KG2];   // norm(relu(y1)) transposed fp16
__device__ float g_Krot1[AO * 27];
__device__ float g_Krot2[AO * 27];
__device__ float g_acc[320];
__device__ float g_mu1[64], g_rs1[64], g_mu2[64], g_rs2[64], g_bmu[32], g_brs[32];

// ---------------- helpers ------------------------------------------------------
__device__ __forceinline__ uint32_t smem_u32(const void* p) {
    uint32_t a;
    asm("{ .reg .u64 t; cvta.to.shared.u64 t, %1; cvt.u32.u64 %0, t; }" : "=r"(a) : "l"(p));
    return a;
}

#define LDMATRIX_X4(r0, r1, r2, r3, addr) \
    asm volatile("ldmatrix.sync.aligned.m8n8.x4.shared.b16 {%0,%1,%2,%3}, [%4];" \
                 : "=r"(r0), "=r"(r1), "=r"(r2), "=r"(r3) : "r"(addr))
#define LDMATRIX_X2(r0, r1, addr) \
    asm volatile("ldmatrix.sync.aligned.m8n8.x2.shared.b16 {%0,%1}, [%2];" \
                 : "=r"(r0), "=r"(r1) : "r"(addr))
#define MMA_F16(c0, c1, c2, c3, a0, a1, a2, a3, b0, b1) \
    asm volatile("mma.sync.aligned.m16n8k16.row.col.f32.f16.f16.f32 " \
                 "{%0,%1,%2,%3}, {%4,%5,%6,%7}, {%8,%9}, {%0,%1,%2,%3};" \
                 : "+f"(c0), "+f"(c1), "+f"(c2), "+f"(c3) \
                 : "r"(a0), "r"(a1), "r"(a2), "r"(a3), "r"(b0), "r"(b1))
#define CP_ASYNC16(dst, src) \
    asm volatile("cp.async.cg.shared.global [%0], [%1], 16;" :: "r"(dst), "l"(src))
#define CP_COMMIT() asm volatile("cp.async.commit_group;" ::: "memory")
#define CP_WAIT1()  asm volatile("cp.async.wait_group 1;" ::: "memory")

// ---------------- small setup kernels -----------------------------------------
__global__ void zero_acc_kernel() {
    int t = threadIdx.x;
    if (t < 320) g_acc[t] = 0.f;
}

__global__ void rbf_kernel(const float* __restrict__ H, const float* __restrict__ Href,
                           float* __restrict__ wout) {
    int t = threadIdx.x;
    if (t >= 144) return;
    int o = t / G_, g = t % G_;
    float M[9];
    #pragma unroll
    for (int i = 0; i < 3; i++)
        #pragma unroll
        for (int k = 0; k < 3; k++) {
            float s = 0.f;
            #pragma unroll
            for (int j = 0; j < 3; j++)
                s += H[o*9 + j*3 + i] * H[g*9 + j*3 + k];
            M[i*3 + k] = s;
        }
    float wv[R_]; float tot = 0.f;
    #pragma unroll
    for (int r = 0; r < R_; r++) {
        float tr = 0.f;
        #pragma unroll
        for (int m = 0; m < 9; m++) tr += M[m] * Href[r*9 + m];
        float c = (tr - 1.f) * 0.5f;
        c = fminf(fmaxf(c, -1.f + 1e-6f), 1.f - 1e-6f);
        float d = acosf(c);
        float ww = expf(-2.f * d * d);
        wv[r] = ww; tot += ww;
    }
    float inv = 1.f / tot;
    #pragma unroll
    for (int r = 0; r < R_; r++) wout[t * R_ + r] = wv[r] * inv;
}

__global__ void computeK_kernel(__half* __restrict__ Ah,
                                const float* __restrict__ Wg, const float* __restrict__ w,
                                int Cin, int total) {
    int stride = gridDim.x * blockDim.x;
    for (int idx = blockIdx.x * blockDim.x + threadIdx.x; idx < total; idx += stride) {
        int cols = Cin * G_;
        int col = idx % cols, row = idx / cols;
        int a = row / G_, o = row % G_;
        int c = col / G_, g = col % G_;
        float s = 0.f;
        #pragma unroll
        for (int r = 0; r < R_; r++)
            s += Wg[(a * Cin + c) * R_ + r] * w[(o * G_ + g) * R_ + r];
        Ah[idx] = __float2half_rn(s);
    }
}

__global__ void rotker_kernel(const float* __restrict__ Ws, const float* __restrict__ H,
                              float* __restrict__ Krot) {
    int t = threadIdx.x;
    if (t >= G_ * 27) return;
    int g = t / 27, v = t % 27;
    int d = v / 9, h = (v / 3) % 3, w = v % 3;
    float cz = (float)(d - 1), cy = (float)(h - 1), cx = (float)(w - 1);
    float pix[3];
    #pragma unroll
    for (int j = 0; j < 3; j++)
        pix[j] = cz * H[g*9 + 0*3 + j] + cy * H[g*9 + 1*3 + j] + cx * H[g*9 + 2*3 + j] + 1.0f;
    float tt[3]; int fi[3];
    #pragma unroll
    for (int j = 0; j < 3; j++) {
        float f = floorf(pix[j]);
        tt[j] = pix[j] - f;
        fi[j] = (int)f;
    }
    float wc[8]; int ic[8];
    int n = 0;
    #pragma unroll
    for (int dz = 0; dz < 2; dz++)
        #pragma unroll
        for (int dy = 0; dy < 2; dy++)
            #pragma unroll
            for (int dx = 0; dx < 2; dx++) {
                int iz = fi[0] + dz, iy = fi[1] + dy, ix = fi[2] + dx;
                bool valid = (iz >= 0 && iz <= 2 && iy >= 0 && iy <= 2 && ix >= 0 && ix <= 2);
                float wz = dz ? tt[0] : 1.f - tt[0];
                float wy = dy ? tt[1] : 1.f - tt[1];
                float wx = dx ? tt[2] : 1.f - tt[2];
                int cz_ = min(max(iz, 0), 2), cy_ = min(max(iy, 0), 2), cx_ = min(max(ix, 0), 2);
                ic[n] = cz_*9 + cy_*3 + cx_;
                wc[n] = valid ? (wz * wy * wx) : 0.f;
                n++;
            }
    for (int c = 0; c < CO; c++) {
        float s = 0.f;
        #pragma unroll
        for (int q = 0; q < 8; q++) s += Ws[c*27 + ic[q]] * wc[q];
        Krot[(c * G_ + g) * 27 + v] = s;
    }
}

// ---------------- conversion/transpose pass ------------------------------------
template <int K, bool NORM>
__global__ void __launch_bounds__(256) convT_kernel(const float* __restrict__ src,
                                                    __half* __restrict__ th,
                                                    const float* __restrict__ mu,
                                                    const float* __restrict__ rs) {
    __shared__ float tile[32][33];
    int b = blockIdx.z, k0 = blockIdx.y * 32, n0 = blockIdx.x * 32;
    int tx = threadIdx.x, ty = threadIdx.y;   // 32 x 8
    #pragma unroll
    for (int i = 0; i < 4; i++) {
        int k = ty + i * 8;
        float v = src[((size_t)(b * K + k0 + k)) * V_ + n0 + tx];
        if (NORM) {
            int c = (k0 + k) / G_;
            float m_ = mu[b * CO + c], r_ = rs[b * CO + c];
            v = fmaxf((v - m_) * r_, 0.f);
        }
        tile[k][tx] = v;
    }
    __syncthreads();
    int tid = ty * 32 + tx;
    #pragma unroll
    for (int i = 0; i < 2; i++) {
        int e = tid + i * 256;
        int n = e >> 4, w = e & 15;
        float v0 = tile[2 * w][n], v1 = tile[2 * w + 1][n];
        __half2 hh;
        hh.x = __float2half_rn(v0);
        hh.y = __float2half_rn(v1);
        size_t base = ((size_t)b * V_ + n0 + n) * K + k0 + 2 * w;
        *(__half2*)(th + base) = hh;
    }
}

// ---------------- mma.sync fp16 GEMM, cp.async 3-stage pipeline ----------------
// C[b][Mtot][V] = A[Mtot][K] @ B[b][V][K]^T ; rows >= 384 -> C1.
#define GST   3
#define GBUF  32768              // per-stage: 16KB A + 16KB B
#define GSMEM (GST * GBUF)
template <int K>
__global__ void __launch_bounds__(256) gemm_h(
    const __half* __restrict__ A, const __half* __restrict__ B,
    float* __restrict__ C0, float* __restrict__ C1) {
    extern __shared__ char smem[];
    uint32_t sbase = smem_u32(smem);

    int tid = threadIdx.x;
    int lane = tid & 31, warp = tid >> 5;
    int wm = warp >> 2;          // 0..1
    int wn = warp & 3;           // 0..3
    int b  = blockIdx.z;
    int m0 = blockIdx.y * 128;
    int n0 = blockIdx.x * 128;

    const __half* Bb = B + (size_t)b * V_ * K;
    const int NT = K / 64;

    float acc[4][4][4];
    #pragma unroll
    for (int i = 0; i < 4; i++)
        #pragma unroll
        for (int j = 0; j < 4; j++)
            #pragma unroll
            for (int q = 0; q < 4; q++) acc[i][j][q] = 0.f;

    // per-thread fixed load geometry
    int lr = tid >> 3, lc = tid & 7;
    uint32_t loff = lr * 128 + ((lc ^ (lr & 7)) << 4);

    auto ldgsts = [&](int ch, int buf) {
        const __half* Ap = A  + ch * 64;
        const __half* Bp = Bb + ch * 64;
        uint32_t base = sbase + buf * GBUF;
        #pragma unroll
        for (int i = 0; i < 4; i++) {
            int r = lr + i * 32;
            uint32_t off = loff + i * 32 * 128;
            CP_ASYNC16(base + off,         Ap + (size_t)(m0 + r) * K + lc * 8);
            CP_ASYNC16(base + 16384 + off, Bp + (size_t)(n0 + r) * K + lc * 8);
        }
    };

    ldgsts(0, 0); CP_COMMIT();
    ldgsts(1, 1); CP_COMMIT();      // NT >= 3 always

    for (int it = 0; it < NT; it++) {
        CP_WAIT1();
        __syncthreads();
        if (it + 2 < NT) ldgsts(it + 2, (it + 2) % GST);
        CP_COMMIT();

        uint32_t aBuf = sbase + (it % GST) * GBUF;
        uint32_t bBuf = aBuf + 16384;
        #pragma unroll
        for (int kk = 0; kk < 4; kk++) {
            uint32_t af[4][4];
            #pragma unroll
            for (int mt = 0; mt < 4; mt++) {
                int row = wm * 64 + mt * 16 + (lane & 7) + ((lane >> 3) & 1) * 8;
                int cc  = kk * 2 + (lane >> 4);
                uint32_t addr = aBuf + row * 128 + ((cc ^ (row & 7)) << 4);
                LDMATRIX_X4(af[mt][0], af[mt][1], af[mt][2], af[mt][3], addr);
            }
            uint32_t bf[4][2];
            #pragma unroll
            for (int nt = 0; nt < 4; nt++) {
                int l = lane & 15;
                int n = wn * 32 + nt * 8 + (l & 7);
                int cc = kk * 2 + (l >> 3);
                uint32_t addr = bBuf + n * 128 + ((cc ^ (n & 7)) << 4);
                LDMATRIX_X2(bf[nt][0], bf[nt][1], addr);
            }
            #pragma unroll
            for (int mt = 0; mt < 4; mt++)
                #pragma unroll
                for (int nt = 0; nt < 4; nt++)
                    MMA_F16(acc[mt][nt][0], acc[mt][nt][1], acc[mt][nt][2], acc[mt][nt][3],
                            af[mt][0], af[mt][1], af[mt][2], af[mt][3],
                            bf[nt][0], bf[nt][1]);
        }
        __syncthreads();
    }

    // epilogue
    float* Cb;
    int mloc;
    if (m0 < AO) { Cb = C0 + (size_t)b * AO * V_; mloc = m0; }
    else         { Cb = C1 + (size_t)b * AO * V_; mloc = m0 - AO; }
    int g = lane >> 2, q = lane & 3;
    int mBase = mloc + wm * 64;
    int nBase = n0 + wn * 32;
    #pragma unroll
    for (int mt = 0; mt < 4; mt++) {
        #pragma unroll
        for (int nt = 0; nt < 4; nt++) {
            int row = mBase + mt * 16 + g;
            int col = nBase + nt * 8 + 2 * q;
            float2 v0 = make_float2(acc[mt][nt][0], acc[mt][nt][1]);
            float2 v1 = make_float2(acc[mt][nt][2], acc[mt][nt][3]);
            *(float2*)(Cb + (size_t)row * V_ + col)       = v0;
            *(float2*)(Cb + (size_t)(row + 8) * V_ + col) = v1;
        }
    }
}

// ---------------- depthwise conv (8 output planes/CTA) + stats ----------------
__global__ void __launch_bounds__(256) dwconv_kernel(const float* __restrict__ src,
                                                     const float* __restrict__ Krot,
                                                     float* __restrict__ dst,
                                                     float* __restrict__ accSum,
                                                     float* __restrict__ accSq) {
    int dg = blockIdx.x;     // 0..3 (8 planes each)
    int ch = blockIdx.y;     // 0..383
    int b  = blockIdx.z;
    const float* zin  = src + ((size_t)(b * AO + ch)) * V_;
    float*       zout = dst + ((size_t)(b * AO + ch)) * V_;

    __shared__ float tile[10][34][34];
    __shared__ float kr[27];
    __shared__ float red[256];

    int tid = threadIdx.x;
    if (tid < 27) kr[tid] = Krot[ch * 27 + tid];

    int z0 = dg * 8;
    for (int e = tid; e < 10 * 1156; e += 256) {
        int p  = e / 1156;
        int rr = (e % 1156) / 34;
        int cc = e % 34;
        int zp = z0 - 1 + p, hh = rr - 1, ww = cc - 1;
        float val = 0.f;
        if (zp >= 0 && zp < 32 && hh >= 0 && hh < 32 && ww >= 0 && ww < 32)
            val = zin[zp * 1024 + hh * 32 + ww];
        tile[p][rr][cc] = val;
    }
    __syncthreads();

    float krr[27];
    #pragma unroll
    for (int m = 0; m < 27; m++) krr[m] = kr[m];

    float lsum = 0.f, lsq = 0.f;
    int tx = tid & 31, ty = tid >> 5;   // 32 x 8
    #pragma unroll
    for (int od = 0; od < 8; od++) {
        for (int hh = ty; hh < 32; hh += 8) {
            float a = 0.f;
            #pragma unroll
            for (int p = 0; p < 3; p++)
                #pragma unroll
                for (int i = 0; i < 3; i++)
                    #pragma unroll
                    for (int j = 0; j < 3; j++)
                        a += tile[od + p][hh + i][tx + j] * krr[p * 9 + i * 3 + j];
            zout[(z0 + od) * 1024 + hh * 32 + tx] = a;
            lsum += a;
            lsq  += a * a;
        }
    }
    red[tid] = lsum; __syncthreads();
    for (int s = 128; s > 0; s >>= 1) { if (tid < s) red[tid] += red[tid + s]; __syncthreads(); }
    float bs = red[0]; __syncthreads();
    red[tid] = lsq; __syncthreads();
    for (int s = 128; s > 0; s >>= 1) { if (tid < s) red[tid] += red[tid + s]; __syncthreads(); }
    if (tid == 0) {
        int idx = b * CO + ch / G_;
        atomicAdd(&accSum[idx], bs);
        atomicAdd(&accSq[idx],  red[0]);
    }
}

__global__ void finstat_kernel(const float* __restrict__ sum, const float* __restrict__ sq,
                               float cnt, int n, float* __restrict__ mu, float* __restrict__ rs) {
    int t = threadIdx.x;
    if (t < n) {
        float m = sum[t] / cnt;
        float v = sq[t] / cnt - m * m;
        mu[t] = m;
        rs[t] = rsqrtf(v + 1e-5f);
    }
}

__global__ void __launch_bounds__(256) combine_kernel() {
    int br  = blockIdx.x;
    int b   = br / AO;
    int row = br % AO;
    int a   = row / G_;
    float mu = g_mu2[b * CO + a], rs = g_rs2[b * CO + a];
    const float4* y2 = (const float4*)(g_bufB + (size_t)br * V_);
    const float4* rv = (const float4*)(g_bufC + (size_t)br * V_);
    float4*       tp = (float4*)(g_bufA + (size_t)br * V_);
    __shared__ float red[256];
    int tid = threadIdx.x;
    int base = blockIdx.y * 512 + tid * 2;
    float lsum = 0.f, lsq = 0.f;
    #pragma unroll
    for (int q = 0; q < 2; q++) {
        int i4 = base + q;
        float4 yv = y2[i4];
        float4 rr = rv[i4];
        float4 o;
        o.x = fmaxf((yv.x - mu) * rs, 0.f) + rr.x;
        o.y = fmaxf((yv.y - mu) * rs, 0.f) + rr.y;
        o.z = fmaxf((yv.z - mu) * rs, 0.f) + rr.z;
        o.w = fmaxf((yv.w - mu) * rs, 0.f) + rr.w;
        tp[i4] = o;
        lsum += o.x + o.y + o.z + o.w;
        lsq  += o.x * o.x + o.y * o.y + o.z * o.z + o.w * o.w;
    }
    red[tid] = lsum; __syncthreads();
    for (int s = 128; s > 0; s >>= 1) { if (tid < s) red[tid] += red[tid + s]; __syncthreads(); }
    float bs = red[0]; __syncthreads();
    red[tid] = lsq; __syncthreads();
    for (int s = 128; s > 0; s >>= 1) { if (tid < s) red[tid] += red[tid + s]; __syncthreads(); }
    if (tid == 0) {
        atomicAdd(&g_acc[256 + a], bs);
        atomicAdd(&g_acc[288 + a], red[0]);
    }
}

__global__ void __launch_bounds__(256) final_kernel(float* __restrict__ out,
                                                    const float* __restrict__ gamma,
                                                    const float* __restrict__ beta) {
    int i4 = blockIdx.x * 256 + threadIdx.x;
    int row = i4 >> 13;
    int a = (row % AO) / G_;
    float mu = g_bmu[a];
    float sc = g_brs[a] * gamma[a];
    float bt = beta[a];
    float4 t = ((const float4*)g_bufA)[i4];
    float4 o;
    o.x = (t.x - mu) * sc + bt;
    o.y = (t.y - mu) * sc + bt;
    o.z = (t.z - mu) * sc + bt;
    o.w = (t.w - mu) * sc + bt;
    ((float4*)out)[i4] = o;
}

// ---------------- launch ------------------------------------------------------
extern "C" void kernel_launch(void* const* d_in, const int* in_sizes, int n_in,
                              void* d_out, int out_size) {
    const float* x      = (const float*)d_in[0];
    const float* H      = (const float*)d_in[1];
    const float* Href1  = (const float*)d_in[2];
    const float* Href2  = (const float*)d_in[3];
    const float* Hrefr  = (const float*)d_in[4];
    const float* Wg1    = (const float*)d_in[5];
    const float* Ws1    = (const float*)d_in[6];
    const float* Wg2    = (const float*)d_in[7];
    const float* Ws2    = (const float*)d_in[8];
    const float* Wres   = (const float*)d_in[9];
    const float* gamma  = (const float*)d_in[10];
    const float* beta   = (const float*)d_in[11];
    float* out = (float*)d_out;

    float *bufA, *bufB, *bufC, *wbuf, *Krot1, *Krot2, *acc;
    float *mu1, *rs1, *mu2, *rs2, *bmu, *brs;
    __half *Acmb1, *A2, *xt, *yt;
    cudaGetSymbolAddress((void**)&bufA,  g_bufA);
    cudaGetSymbolAddress((void**)&bufB,  g_bufB);
    cudaGetSymbolAddress((void**)&bufC,  g_bufC);
    cudaGetSymbolAddress((void**)&wbuf,  g_w);
    cudaGetSymbolAddress((void**)&Acmb1, g_Acmb1);
    cudaGetSymbolAddress((void**)&A2,    g_A2);
    cudaGetSymbolAddress((void**)&xt,    g_xt);
    cudaGetSymbolAddress((void**)&yt,    g_yt);
    cudaGetSymbolAddress((void**)&Krot1, g_Krot1);
    cudaGetSymbolAddress((void**)&Krot2, g_Krot2);
    cudaGetSymbolAddress((void**)&acc,   g_acc);
    cudaGetSymbolAddress((void**)&mu1,   g_mu1);
    cudaGetSymbolAddress((void**)&rs1,   g_rs1);
    cudaGetSymbolAddress((void**)&mu2,   g_mu2);
    cudaGetSymbolAddress((void**)&rs2,   g_rs2);
    cudaGetSymbolAddress((void**)&bmu,   g_bmu);
    cudaGetSymbolAddress((void**)&brs,   g_brs);

    cudaFuncSetAttribute(gemm_h<KG1>, cudaFuncAttributeMaxDynamicSharedMemorySize, GSMEM);
    cudaFuncSetAttribute(gemm_h<KG2>, cudaFuncAttributeMaxDynamicSharedMemorySize, GSMEM);

    zero_acc_kernel<<<1, 320>>>();
    rbf_kernel<<<1, 144>>>(H, Href1, wbuf);
    rbf_kernel<<<1, 144>>>(H, Href2, wbuf + 1728);
    rbf_kernel<<<1, 144>>>(H, Hrefr, wbuf + 2 * 1728);
    computeK_kernel<<<288, 256>>>(Acmb1,            Wg1,  wbuf,            CI, AO * KG1);
    computeK_kernel<<<576, 256>>>(A2,               Wg2,  wbuf + 1728,     CO, AO * KG2);
    computeK_kernel<<<288, 256>>>(Acmb1 + AO * KG1, Wres, wbuf + 2 * 1728, CI, AO * KG1);
    rotker_kernel<<<1, 324>>>(Ws1, H, Krot1);
    rotker_kernel<<<1, 324>>>(Ws2, H, Krot2);

    // x -> fp16 transposed [b][v][k]
    convT_kernel<KG1, false><<<dim3(1024, 6, 2), dim3(32, 8)>>>(x, xt, nullptr, nullptr);

    // fused: [z1 ; res] = [K1 ; Kres] @ x   (M = 768)
    gemm_h<KG1><<<dim3(256, 6, 2), 256, GSMEM>>>(Acmb1, xt, bufA, bufC);
    // y1 = dwconv(z1) + stats
    dwconv_kernel<<<dim3(4, 384, 2), 256>>>(bufA, Krot1, bufB, acc + 0, acc + 64);
    finstat_kernel<<<1, 64>>>(acc + 0, acc + 64, (float)(G_ * V_), 64, mu1, rs1);
    // relu(instnorm(y1)) -> fp16 transposed
    convT_kernel<KG2, true><<<dim3(1024, 12, 2), dim3(32, 8)>>>(bufB, yt, mu1, rs1);
    // z2 = K2 @ (.)
    gemm_h<KG2><<<dim3(256, 3, 2), 256, GSMEM>>>(A2, yt, bufA, bufA);
    // y2 = dwconv(z2) + stats
    dwconv_kernel<<<dim3(4, 384, 2), 256>>>(bufA, Krot2, bufB, acc + 128, acc + 192);
    finstat_kernel<<<1, 64>>>(acc + 128, acc + 192, (float)(G_ * V_), 64, mu2, rs2);
    // t = relu(instnorm(y2)) + res, + bn stats
    combine_kernel<<<dim3(768, 16), 256>>>();
    finstat_kernel<<<1, 32>>>(acc + 256, acc + 288, (float)(B_ * G_ * V_), 32, bmu, brs);
    // out = batchnorm(t)
    final_kernel<<<24576, 256>>>(out, gamma, beta);
    cudaMemcpyAsync(out + NY, H, 108 * sizeof(float), cudaMemcpyDeviceToDevice);
}

// round 8
// speedup vs baseline: 2.5756x; 1.0405x over previous
#include <cuda_runtime.h>
#include <cuda_fp16.h>
#include <cstdint>
#include <math.h>

// Problem constants
#define B_   2
#define CI   16
#define CO   32
#define G_   12
#define R_   12
#define S_   32
#define V_   32768          // 32^3
#define AO   384            // Co*G
#define KG1  192            // Ci*G
#define KG2  384            // Co*G
#define NY   25165824       // B*Co*G*V  (y element count)

// ---------------- scratch (device globals; no allocation allowed) -------------
__device__ float  g_tf[(size_t)B_ * AO * V_];        // t (combine out, fp32)
__device__ __half g_zh[(size_t)B_ * AO * V_];        // z1 / z2
__device__ __half g_resh[(size_t)B_ * AO * V_];      // residual
__device__ __half g_yh[(size_t)B_ * AO * V_];        // y1 / y2
__device__ float  g_w[3 * 144 * R_];
__device__ __half g_Acmb1[2 * AO * KG1];             // [K1 ; Kres]  (768 x 192)
__device__ __half g_A2[AO * KG2];                    // 384 x 384
__device__ __half g_xt[(size_t)B_ * V_ * KG1];       // x transposed fp16 [b][v][k]
__device__ __half g_yt[(size_t)B_ * V_ * KG2];       // norm(relu(y1)) transposed fp16
__device__ float  g_Krot1[AO * 27];
__device__ float  g_Krot2[AO * 27];
__device__ float  g_acc[320];
__device__ float  g_mu1[64], g_rs1[64], g_mu2[64], g_rs2[64], g_bmu[32], g_brs[32];

// ---------------- helpers ------------------------------------------------------
__device__ __forceinline__ uint32_t smem_u32(const void* p) {
    uint32_t a;
    asm("{ .reg .u64 t; cvta.to.shared.u64 t, %1; cvt.u32.u64 %0, t; }" : "=r"(a) : "l"(p));
    return a;
}

#define LDMATRIX_X4(r0, r1, r2, r3, addr) \
    asm volatile("ldmatrix.sync.aligned.m8n8.x4.shared.b16 {%0,%1,%2,%3}, [%4];" \
                 : "=r"(r0), "=r"(r1), "=r"(r2), "=r"(r3) : "r"(addr))
#define LDMATRIX_X2(r0, r1, addr) \
    asm volatile("ldmatrix.sync.aligned.m8n8.x2.shared.b16 {%0,%1}, [%2];" \
                 : "=r"(r0), "=r"(r1) : "r"(addr))
#define MMA_F16(c0, c1, c2, c3, a0, a1, a2, a3, b0, b1) \
    asm volatile("mma.sync.aligned.m16n8k16.row.col.f32.f16.f16.f32 " \
                 "{%0,%1,%2,%3}, {%4,%5,%6,%7}, {%8,%9}, {%0,%1,%2,%3};" \
                 : "+f"(c0), "+f"(c1), "+f"(c2), "+f"(c3) \
                 : "r"(a0), "r"(a1), "r"(a2), "r"(a3), "r"(b0), "r"(b1))
#define CP_ASYNC16(dst, src) \
    asm volatile("cp.async.cg.shared.global [%0], [%1], 16;" :: "r"(dst), "l"(src))
#define CP_COMMIT() asm volatile("cp.async.commit_group;" ::: "memory")
#define CP_WAIT1()  asm volatile("cp.async.wait_group 1;" ::: "memory")

// ---------------- merged setup kernel -----------------------------------------
// blocks 0..2: rbf(w segment i);  blocks 3..4: rotker;  block 5: zero acc
__global__ void setup_kernel(const float* __restrict__ H,
                             const float* __restrict__ Href1,
                             const float* __restrict__ Href2,
                             const float* __restrict__ Hrefr,
                             const float* __restrict__ Ws1,
                             const float* __restrict__ Ws2) {
    int blk = blockIdx.x;
    int t = threadIdx.x;
    if (blk < 3) {
        if (t >= 144) return;
        const float* Href = (blk == 0) ? Href1 : (blk == 1) ? Href2 : Hrefr;
        float* wout = g_w + blk * 1728;
        int o = t / G_, g = t % G_;
        float M[9];
        #pragma unroll
        for (int i = 0; i < 3; i++)
            #pragma unroll
            for (int k = 0; k < 3; k++) {
                float s = 0.f;
                #pragma unroll
                for (int j = 0; j < 3; j++)
                    s += H[o*9 + j*3 + i] * H[g*9 + j*3 + k];
                M[i*3 + k] = s;
            }
        float wv[R_]; float tot = 0.f;
        #pragma unroll
        for (int r = 0; r < R_; r++) {
            float tr = 0.f;
            #pragma unroll
            for (int m = 0; m < 9; m++) tr += M[m] * Href[r*9 + m];
            float c = (tr - 1.f) * 0.5f;
            c = fminf(fmaxf(c, -1.f + 1e-6f), 1.f - 1e-6f);
            float d = acosf(c);
            float ww = expf(-2.f * d * d);
            wv[r] = ww; tot += ww;
        }
        float inv = 1.f / tot;
        #pragma unroll
        for (int r = 0; r < R_; r++) wout[t * R_ + r] = wv[r] * inv;
    } else if (blk < 5) {
        if (t >= G_ * 27) return;
        const float* Ws = (blk == 3) ? Ws1 : Ws2;
        float* Krot = (blk == 3) ? g_Krot1 : g_Krot2;
        int g = t / 27, v = t % 27;
        int d = v / 9, h = (v / 3) % 3, w = v % 3;
        float cz = (float)(d - 1), cy = (float)(h - 1), cx = (float)(w - 1);
        float pix[3];
        #pragma unroll
        for (int j = 0; j < 3; j++)
            pix[j] = cz * H[g*9 + 0*3 + j] + cy * H[g*9 + 1*3 + j] + cx * H[g*9 + 2*3 + j] + 1.0f;
        float tt[3]; int fi[3];
        #pragma unroll
        for (int j = 0; j < 3; j++) {
            float f = floorf(pix[j]);
            tt[j] = pix[j] - f;
            fi[j] = (int)f;
        }
        float wc[8]; int ic[8];
        int n = 0;
        #pragma unroll
        for (int dz = 0; dz < 2; dz++)
            #pragma unroll
            for (int dy = 0; dy < 2; dy++)
                #pragma unroll
                for (int dx = 0; dx < 2; dx++) {
                    int iz = fi[0] + dz, iy = fi[1] + dy, ix = fi[2] + dx;
                    bool valid = (iz >= 0 && iz <= 2 && iy >= 0 && iy <= 2 && ix >= 0 && ix <= 2);
                    float wz = dz ? tt[0] : 1.f - tt[0];
                    float wy = dy ? tt[1] : 1.f - tt[1];
                    float wx = dx ? tt[2] : 1.f - tt[2];
                    int cz_ = min(max(iz, 0), 2), cy_ = min(max(iy, 0), 2), cx_ = min(max(ix, 0), 2);
                    ic[n] = cz_*9 + cy_*3 + cx_;
                    wc[n] = valid ? (wz * wy * wx) : 0.f;
                    n++;
                }
        for (int c = 0; c < CO; c++) {
            float s = 0.f;
            #pragma unroll
            for (int q = 0; q < 8; q++) s += Ws[c*27 + ic[q]] * wc[q];
            Krot[(c * G_ + g) * 27 + v] = s;
        }
    } else {
        if (t < 320) g_acc[t] = 0.f;
    }
}

// merged K-matrix build: [K1 | A2 | Kres] in one grid-stride pass
#define NK1 (AO * KG1)
#define NK2 (AO * KG2)
__global__ void computeK_all(const float* __restrict__ Wg1,
                             const float* __restrict__ Wg2,
                             const float* __restrict__ Wres) {
    int total = 2 * NK1 + NK2;
    int stride = gridDim.x * blockDim.x;
    for (int gi = blockIdx.x * blockDim.x + threadIdx.x; gi < total; gi += stride) {
        const float* Wg; const float* w; __half* dst; int Cin, idx;
        if (gi < NK1)            { Wg = Wg1;  w = g_w;        dst = g_Acmb1;       Cin = CI; idx = gi; }
        else if (gi < NK1 + NK2) { Wg = Wg2;  w = g_w + 1728; dst = g_A2;          Cin = CO; idx = gi - NK1; }
        else                     { Wg = Wres; w = g_w + 3456; dst = g_Acmb1 + NK1; Cin = CI; idx = gi - NK1 - NK2; }
        int cols = Cin * G_;
        int col = idx % cols, row = idx / cols;
        int a = row / G_, o = row % G_;
        int c = col / G_, g = col % G_;
        float s = 0.f;
        #pragma unroll
        for (int r = 0; r < R_; r++)
            s += Wg[(a * Cin + c) * R_ + r] * w[(o * G_ + g) * R_ + r];
        dst[idx] = __float2half_rn(s);
    }
}

// ---------------- conversion/transpose pass ------------------------------------
// src [b][K][V] (float or half) -> t [b][V][K] fp16 (optionally fused inst-norm+relu)
template <int K, bool NORM, typename Ti>
__global__ void __launch_bounds__(256) convT_kernel(const Ti* __restrict__ src,
                                                    __half* __restrict__ th,
                                                    const float* __restrict__ mu,
                                                    const float* __restrict__ rs) {
    __shared__ float tile[32][33];
    int b = blockIdx.z, k0 = blockIdx.y * 32, n0 = blockIdx.x * 32;
    int tx = threadIdx.x, ty = threadIdx.y;   // 32 x 8
    #pragma unroll
    for (int i = 0; i < 4; i++) {
        int k = ty + i * 8;
        float v = (float)src[((size_t)(b * K + k0 + k)) * V_ + n0 + tx];
        if (NORM) {
            int c = (k0 + k) / G_;
            float m_ = mu[b * CO + c], r_ = rs[b * CO + c];
            v = fmaxf((v - m_) * r_, 0.f);
        }
        tile[k][tx] = v;
    }
    __syncthreads();
    int tid = ty * 32 + tx;
    #pragma unroll
    for (int i = 0; i < 2; i++) {
        int e = tid + i * 256;
        int n = e >> 4, w = e & 15;
        __half2 hh;
        hh.x = __float2half_rn(tile[2 * w][n]);
        hh.y = __float2half_rn(tile[2 * w + 1][n]);
        size_t base = ((size_t)b * V_ + n0 + n) * K + k0 + 2 * w;
        *(__half2*)(th + base) = hh;
    }
}

// ---------------- mma.sync fp16 GEMM, cp.async 3-stage pipeline ----------------
// C[b][Mtot][V] = A[Mtot][K] @ B[b][V][K]^T ; rows >= 384 -> C1.  fp16 output.
#define GST   3
#define GBUF  32768              // per-stage: 16KB A + 16KB B
#define GSMEM (GST * GBUF)
template <int K>
__global__ void __launch_bounds__(256) gemm_h(
    const __half* __restrict__ A, const __half* __restrict__ B,
    __half* __restrict__ C0, __half* __restrict__ C1) {
    extern __shared__ char smem[];
    uint32_t sbase = smem_u32(smem);

    int tid = threadIdx.x;
    int lane = tid & 31, warp = tid >> 5;
    int wm = warp >> 2;          // 0..1
    int wn = warp & 3;           // 0..3
    int b  = blockIdx.z;
    int m0 = blockIdx.y * 128;
    int n0 = blockIdx.x * 128;

    const __half* Bb = B + (size_t)b * V_ * K;
    const int NT = K / 64;

    float acc[4][4][4];
    #pragma unroll
    for (int i = 0; i < 4; i++)
        #pragma unroll
        for (int j = 0; j < 4; j++)
            #pragma unroll
            for (int q = 0; q < 4; q++) acc[i][j][q] = 0.f;

    int lr = tid >> 3, lc = tid & 7;
    uint32_t loff = lr * 128 + ((lc ^ (lr & 7)) << 4);

    auto ldgsts = [&](int ch, int buf) {
        const __half* Ap = A  + ch * 64;
        const __half* Bp = Bb + ch * 64;
        uint32_t base = sbase + buf * GBUF;
        #pragma unroll
        for (int i = 0; i < 4; i++) {
            int r = lr + i * 32;
            uint32_t off = loff + i * 32 * 128;
            CP_ASYNC16(base + off,         Ap + (size_t)(m0 + r) * K + lc * 8);
            CP_ASYNC16(base + 16384 + off, Bp + (size_t)(n0 + r) * K + lc * 8);
        }
    };

    ldgsts(0, 0); CP_COMMIT();
    ldgsts(1, 1); CP_COMMIT();

    for (int it = 0; it < NT; it++) {
        CP_WAIT1();
        __syncthreads();
        if (it + 2 < NT) ldgsts(it + 2, (it + 2) % GST);
        CP_COMMIT();

        uint32_t aBuf = sbase + (it % GST) * GBUF;
        uint32_t bBuf = aBuf + 16384;
        #pragma unroll
        for (int kk = 0; kk < 4; kk++) {
            uint32_t af[4][4];
            #pragma unroll
            for (int mt = 0; mt < 4; mt++) {
                int row = wm * 64 + mt * 16 + (lane & 7) + ((lane >> 3) & 1) * 8;
                int cc  = kk * 2 + (lane >> 4);
                uint32_t addr = aBuf + row * 128 + ((cc ^ (row & 7)) << 4);
                LDMATRIX_X4(af[mt][0], af[mt][1], af[mt][2], af[mt][3], addr);
            }
            uint32_t bf[4][2];
            #pragma unroll
            for (int nt = 0; nt < 4; nt++) {
                int l = lane & 15;
                int n = wn * 32 + nt * 8 + (l & 7);
                int cc = kk * 2 + (l >> 3);
                uint32_t addr = bBuf + n * 128 + ((cc ^ (n & 7)) << 4);
                LDMATRIX_X2(bf[nt][0], bf[nt][1], addr);
            }
            #pragma unroll
            for (int mt = 0; mt < 4; mt++)
                #pragma unroll
                for (int nt = 0; nt < 4; nt++)
                    MMA_F16(acc[mt][nt][0], acc[mt][nt][1], acc[mt][nt][2], acc[mt][nt][3],
                            af[mt][0], af[mt][1], af[mt][2], af[mt][3],
                            bf[nt][0], bf[nt][1]);
        }
        __syncthreads();
    }

    // epilogue: fp16 stores
    __half* Cb;
    int mloc;
    if (m0 < AO) { Cb = C0 + (size_t)b * AO * V_; mloc = m0; }
    else         { Cb = C1 + (size_t)b * AO * V_; mloc = m0 - AO; }
    int g = lane >> 2, q = lane & 3;
    int mBase = mloc + wm * 64;
    int nBase = n0 + wn * 32;
    #pragma unroll
    for (int mt = 0; mt < 4; mt++) {
        #pragma unroll
        for (int nt = 0; nt < 4; nt++) {
            int row = mBase + mt * 16 + g;
            int col = nBase + nt * 8 + 2 * q;
            __half2 h0 = __floats2half2_rn(acc[mt][nt][0], acc[mt][nt][1]);
            __half2 h1 = __floats2half2_rn(acc[mt][nt][2], acc[mt][nt][3]);
            *(__half2*)(Cb + (size_t)row * V_ + col)       = h0;
            *(__half2*)(Cb + (size_t)(row + 8) * V_ + col) = h1;
        }
    }
}

// ---------------- depthwise conv (8 planes/CTA, fp16 I/O) + stats -------------
__global__ void __launch_bounds__(256) dwconv_kernel(const __half* __restrict__ src,
                                                     const float* __restrict__ Krot,
                                                     __half* __restrict__ dst,
                                                     float* __restrict__ accSum,
                                                     float* __restrict__ accSq) {
    int dg = blockIdx.x;     // 0..3 (8 planes each)
    int ch = blockIdx.y;     // 0..383
    int b  = blockIdx.z;
    const __half* zin  = src + ((size_t)(b * AO + ch)) * V_;
    __half*       zout = dst + ((size_t)(b * AO + ch)) * V_;

    __shared__ float tile[10][34][34];
    __shared__ float kr[27];
    __shared__ float red[256];

    int tid = threadIdx.x;
    if (tid < 27) kr[tid] = Krot[ch * 27 + tid];

    int z0 = dg * 8;
    for (int e = tid; e < 10 * 1156; e += 256) {
        int p  = e / 1156;
        int rr = (e % 1156) / 34;
        int cc = e % 34;
        int zp = z0 - 1 + p, hh = rr - 1, ww = cc - 1;
        float val = 0.f;
        if (zp >= 0 && zp < 32 && hh >= 0 && hh < 32 && ww >= 0 && ww < 32)
            val = __half2float(zin[zp * 1024 + hh * 32 + ww]);
        tile[p][rr][cc] = val;
    }
    __syncthreads();

    float krr[27];
    #pragma unroll
    for (int m = 0; m < 27; m++) krr[m] = kr[m];

    float lsum = 0.f, lsq = 0.f;
    int tx = tid & 31, ty = tid >> 5;   // 32 x 8
    #pragma unroll
    for (int od = 0; od < 8; od++) {
        for (int hh = ty; hh < 32; hh += 8) {
            float a = 0.f;
            #pragma unroll
            for (int p = 0; p < 3; p++)
                #pragma unroll
                for (int i = 0; i < 3; i++)
                    #pragma unroll
                    for (int j = 0; j < 3; j++)
                        a += tile[od + p][hh + i][tx + j] * krr[p * 9 + i * 3 + j];
            zout[(z0 + od) * 1024 + hh * 32 + tx] = __float2half_rn(a);
            lsum += a;
            lsq  += a * a;
        }
    }
    red[tid] = lsum; __syncthreads();
    for (int s = 128; s > 0; s >>= 1) { if (tid < s) red[tid] += red[tid + s]; __syncthreads(); }
    float bs = red[0]; __syncthreads();
    red[tid] = lsq; __syncthreads();
    for (int s = 128; s > 0; s >>= 1) { if (tid < s) red[tid] += red[tid + s]; __syncthreads(); }
    if (tid == 0) {
        int idx = b * CO + ch / G_;
        atomicAdd(&accSum[idx], bs);
        atomicAdd(&accSq[idx],  red[0]);
    }
}

__global__ void finstat_kernel(const float* __restrict__ sum, const float* __restrict__ sq,
                               float cnt, int n, float* __restrict__ mu, float* __restrict__ rs) {
    int t = threadIdx.x;
    if (t < n) {
        float m = sum[t] / cnt;
        float v = sq[t] / cnt - m * m;
        mu[t] = m;
        rs[t] = rsqrtf(v + 1e-5f);
    }
}

// t = relu(instnorm(y2)) + res ; batchnorm stats.  y2/res fp16, t fp32.
__global__ void __launch_bounds__(256) combine_kernel() {
    int br  = blockIdx.x;
    int b   = br / AO;
    int row = br % AO;
    int a   = row / G_;
    float mu = g_mu2[b * CO + a], rs = g_rs2[b * CO + a];
    const __half2* y2 = (const __half2*)(g_yh   + (size_t)br * V_);
    const __half2* rv = (const __half2*)(g_resh + (size_t)br * V_);
    float2*        tp = (float2*)(g_tf + (size_t)br * V_);
    __shared__ float red[256];
    int tid = threadIdx.x;
    int base2 = blockIdx.y * 1024 + tid * 4;    // half2 units (V/2 = 16384 per row)
    float lsum = 0.f, lsq = 0.f;
    #pragma unroll
    for (int q = 0; q < 4; q++) {
        int i2 = base2 + q;
        float2 yv = __half22float2(y2[i2]);
        float2 rr = __half22float2(rv[i2]);
        float2 o;
        o.x = fmaxf((yv.x - mu) * rs, 0.f) + rr.x;
        o.y = fmaxf((yv.y - mu) * rs, 0.f) + rr.y;
        tp[i2] = o;
        lsum += o.x + o.y;
        lsq  += o.x * o.x + o.y * o.y;
    }
    red[tid] = lsum; __syncthreads();
    for (int s = 128; s > 0; s >>= 1) { if (tid < s) red[tid] += red[tid + s]; __syncthreads(); }
    float bs = red[0]; __syncthreads();
    red[tid] = lsq; __syncthreads();
    for (int s = 128; s > 0; s >>= 1) { if (tid < s) red[tid] += red[tid + s]; __syncthreads(); }
    if (tid == 0) {
        atomicAdd(&g_acc[256 + a], bs);
        atomicAdd(&g_acc[288 + a], red[0]);
    }
}

__global__ void __launch_bounds__(256) final_kernel(float* __restrict__ out,
                                                    const float* __restrict__ gamma,
                                                    const float* __restrict__ beta) {
    int i4 = blockIdx.x * 256 + threadIdx.x;
    int row = i4 >> 13;
    int a = (row % AO) / G_;
    float mu = g_bmu[a];
    float sc = g_brs[a] * gamma[a];
    float bt = beta[a];
    float4 t = ((const float4*)g_tf)[i4];
    float4 o;
    o.x = (t.x - mu) * sc + bt;
    o.y = (t.y - mu) * sc + bt;
    o.z = (t.z - mu) * sc + bt;
    o.w = (t.w - mu) * sc + bt;
    ((float4*)out)[i4] = o;
}

// ---------------- launch ------------------------------------------------------
extern "C" void kernel_launch(void* const* d_in, const int* in_sizes, int n_in,
                              void* d_out, int out_size) {
    const float* x      = (const float*)d_in[0];
    const float* H      = (const float*)d_in[1];
    const float* Href1  = (const float*)d_in[2];
    const float* Href2  = (const float*)d_in[3];
    const float* Hrefr  = (const float*)d_in[4];
    const float* Wg1    = (const float*)d_in[5];
    const float* Ws1    = (const float*)d_in[6];
    const float* Wg2    = (const float*)d_in[7];
    const float* Ws2    = (const float*)d_in[8];
    const float* Wres   = (const float*)d_in[9];
    const float* gamma  = (const float*)d_in[10];
    const float* beta   = (const float*)d_in[11];
    float* out = (float*)d_out;

    float *Krot1, *Krot2, *acc, *mu1, *rs1, *mu2, *rs2, *bmu, *brs;
    __half *Acmb1, *A2, *xt, *yt, *zh, *resh, *yh;
    cudaGetSymbolAddress((void**)&Acmb1, g_Acmb1);
    cudaGetSymbolAddress((void**)&A2,    g_A2);
    cudaGetSymbolAddress((void**)&xt,    g_xt);
    cudaGetSymbolAddress((void**)&yt,    g_yt);
    cudaGetSymbolAddress((void**)&zh,    g_zh);
    cudaGetSymbolAddress((void**)&resh,  g_resh);
    cudaGetSymbolAddress((void**)&yh,    g_yh);
    cudaGetSymbolAddress((void**)&Krot1, g_Krot1);
    cudaGetSymbolAddress((void**)&Krot2, g_Krot2);
    cudaGetSymbolAddress((void**)&acc,   g_acc);
    cudaGetSymbolAddress((void**)&mu1,   g_mu1);
    cudaGetSymbolAddress((void**)&rs1,   g_rs1);
    cudaGetSymbolAddress((void**)&mu2,   g_mu2);
    cudaGetSymbolAddress((void**)&rs2,   g_rs2);
    cudaGetSymbolAddress((void**)&bmu,   g_bmu);
    cudaGetSymbolAddress((void**)&brs,   g_brs);

    cudaFuncSetAttribute(gemm_h<KG1>, cudaFuncAttributeMaxDynamicSharedMemorySize, GSMEM);
    cudaFuncSetAttribute(gemm_h<KG2>, cudaFuncAttributeMaxDynamicSharedMemorySize, GSMEM);

    setup_kernel<<<6, 352>>>(H, Href1, Href2, Hrefr, Ws1, Ws2);
    computeK_all<<<1152, 256>>>(Wg1, Wg2, Wres);

    // x -> fp16 transposed [b][v][k]
    convT_kernel<KG1, false, float><<<dim3(1024, 6, 2), dim3(32, 8)>>>(x, xt, nullptr, nullptr);

    // fused: [z1 ; res] = [K1 ; Kres] @ x   (M = 768)
    gemm_h<KG1><<<dim3(256, 6, 2), 256, GSMEM>>>(Acmb1, xt, zh, resh);
    // y1 = dwconv(z1) + stats
    dwconv_kernel<<<dim3(4, 384, 2), 256>>>(zh, Krot1, yh, acc + 0, acc + 64);
    finstat_kernel<<<1, 64>>>(acc + 0, acc + 64, (float)(G_ * V_), 64, mu1, rs1);
    // relu(instnorm(y1)) -> fp16 transposed
    convT_kernel<KG2, true, __half><<<dim3(1024, 12, 2), dim3(32, 8)>>>(yh, yt, mu1, rs1);
    // z2 = K2 @ (.)
    gemm_h<KG2><<<dim3(256, 3, 2), 256, GSMEM>>>(A2, yt, zh, zh);
    // y2 = dwconv(z2) + stats
    dwconv_kernel<<<dim3(4, 384, 2), 256>>>(zh, Krot2, yh, acc + 128, acc + 192);
    finstat_kernel<<<1, 64>>>(acc + 128, acc + 192, (float)(G_ * V_), 64, mu2, rs2);
    // t = relu(instnorm(y2)) + res, + bn stats
    combine_kernel<<<dim3(768, 16), 256>>>();
    finstat_kernel<<<1, 32>>>(acc + 256, acc + 288, (float)(B_ * G_ * V_), 32, bmu, brs);
    // out = batchnorm(t)
    final_kernel<<<24576, 256>>>(out, gamma, beta);
    cudaMemcpyAsync(out + NY, H, 108 * sizeof(float), cudaMemcpyDeviceToDevice);
}

// round 10
// speedup vs baseline: 3.4884x; 1.3544x over previous
#include <cuda_runtime.h>
#include <cuda_fp16.h>
#include <cstdint>
#include <math.h>

// Problem constants
#define B_   2
#define CI   16
#define CO   32
#define G_   12
#define R_   12
#define S_   32
#define V_   32768          // 32^3
#define AO   384            // Co*G
#define KG1  192            // Ci*G
#define KG2  384            // Co*G
#define NY   25165824       // B*Co*G*V  (y element count)

// ---------------- scratch (device globals; no allocation allowed) -------------
__device__ __half g_zh[(size_t)B_ * AO * V_];        // z1 / z2
__device__ __half g_resh[(size_t)B_ * AO * V_];      // residual
__device__ __half g_yh[(size_t)B_ * AO * V_];        // y1 / y2
__device__ float  g_w[3 * 144 * R_];
__device__ __half g_Acmb1[2 * AO * KG1];             // [K1 ; Kres]  (768 x 192)
__device__ __half g_A2[AO * KG2];                    // 384 x 384
__device__ __half g_xt[(size_t)B_ * V_ * KG1];       // x transposed fp16 [b][v][k]
__device__ __half g_yt[(size_t)B_ * V_ * KG2];       // norm(relu(y1)) transposed fp16
__device__ float  g_Krot1[AO * 27];
__device__ float  g_Krot2[AO * 27];
__device__ float  g_acc[320];
__device__ float  g_mu1[64], g_rs1[64], g_mu2[64], g_rs2[64], g_bmu[32], g_brs[32];

// ---------------- helpers ------------------------------------------------------
__device__ __forceinline__ uint32_t smem_u32(const void* p) {
    uint32_t a;
    asm("{ .reg .u64 t; cvta.to.shared.u64 t, %1; cvt.u32.u64 %0, t; }" : "=r"(a) : "l"(p));
    return a;
}

#define LDMATRIX_X4(r0, r1, r2, r3, addr) \
    asm volatile("ldmatrix.sync.aligned.m8n8.x4.shared.b16 {%0,%1,%2,%3}, [%4];" \
                 : "=r"(r0), "=r"(r1), "=r"(r2), "=r"(r3) : "r"(addr))
#define MMA_F16(c0, c1, c2, c3, a0, a1, a2, a3, b0, b1) \
    asm volatile("mma.sync.aligned.m16n8k16.row.col.f32.f16.f16.f32 " \
                 "{%0,%1,%2,%3}, {%4,%5,%6,%7}, {%8,%9}, {%0,%1,%2,%3};" \
                 : "+f"(c0), "+f"(c1), "+f"(c2), "+f"(c3) \
                 : "r"(a0), "r"(a1), "r"(a2), "r"(a3), "r"(b0), "r"(b1))
#define CP_ASYNC16(dst, src) \
    asm volatile("cp.async.cg.shared.global [%0], [%1], 16;" :: "r"(dst), "l"(src))
#define CP_COMMIT() asm volatile("cp.async.commit_group;" ::: "memory")
#define CP_WAIT1()  asm volatile("cp.async.wait_group 1;" ::: "memory")

// ---------------- merged setup kernel -----------------------------------------
__global__ void setup_kernel(const float* __restrict__ H,
                             const float* __restrict__ Href1,
                             const float* __restrict__ Href2,
                             const float* __restrict__ Hrefr,
                             const float* __restrict__ Ws1,
                             const float* __restrict__ Ws2) {
    int blk = blockIdx.x;
    int t = threadIdx.x;
    if (blk < 3) {
        if (t >= 144) return;
        const float* Href = (blk == 0) ? Href1 : (blk == 1) ? Href2 : Hrefr;
        float* wout = g_w + blk * 1728;
        int o = t / G_, g = t % G_;
        float M[9];
        #pragma unroll
        for (int i = 0; i < 3; i++)
            #pragma unroll
            for (int k = 0; k < 3; k++) {
                float s = 0.f;
                #pragma unroll
                for (int j = 0; j < 3; j++)
                    s += H[o*9 + j*3 + i] * H[g*9 + j*3 + k];
                M[i*3 + k] = s;
            }
        float wv[R_]; float tot = 0.f;
        #pragma unroll
        for (int r = 0; r < R_; r++) {
            float tr = 0.f;
            #pragma unroll
            for (int m = 0; m < 9; m++) tr += M[m] * Href[r*9 + m];
            float c = (tr - 1.f) * 0.5f;
            c = fminf(fmaxf(c, -1.f + 1e-6f), 1.f - 1e-6f);
            float d = acosf(c);
            float ww = expf(-2.f * d * d);
            wv[r] = ww; tot += ww;
        }
        float inv = 1.f / tot;
        #pragma unroll
        for (int r = 0; r < R_; r++) wout[t * R_ + r] = wv[r] * inv;
    } else if (blk < 5) {
        if (t >= G_ * 27) return;
        const float* Ws = (blk == 3) ? Ws1 : Ws2;
        float* Krot = (blk == 3) ? g_Krot1 : g_Krot2;
        int g = t / 27, v = t % 27;
        int d = v / 9, h = (v / 3) % 3, w = v % 3;
        float cz = (float)(d - 1), cy = (float)(h - 1), cx = (float)(w - 1);
        float pix[3];
        #pragma unroll
        for (int j = 0; j < 3; j++)
            pix[j] = cz * H[g*9 + 0*3 + j] + cy * H[g*9 + 1*3 + j] + cx * H[g*9 + 2*3 + j] + 1.0f;
        float tt[3]; int fi[3];
        #pragma unroll
        for (int j = 0; j < 3; j++) {
            float f = floorf(pix[j]);
            tt[j] = pix[j] - f;
            fi[j] = (int)f;
        }
        float wc[8]; int ic[8];
        int n = 0;
        #pragma unroll
        for (int dz = 0; dz < 2; dz++)
            #pragma unroll
            for (int dy = 0; dy < 2; dy++)
                #pragma unroll
                for (int dx = 0; dx < 2; dx++) {
                    int iz = fi[0] + dz, iy = fi[1] + dy, ix = fi[2] + dx;
                    bool valid = (iz >= 0 && iz <= 2 && iy >= 0 && iy <= 2 && ix >= 0 && ix <= 2);
                    float wz = dz ? tt[0] : 1.f - tt[0];
                    float wy = dy ? tt[1] : 1.f - tt[1];
                    float wx = dx ? tt[2] : 1.f - tt[2];
                    int cz_ = min(max(iz, 0), 2), cy_ = min(max(iy, 0), 2), cx_ = min(max(ix, 0), 2);
                    ic[n] = cz_*9 + cy_*3 + cx_;
                    wc[n] = valid ? (wz * wy * wx) : 0.f;
                    n++;
                }
        for (int c = 0; c < CO; c++) {
            float s = 0.f;
            #pragma unroll
            for (int q = 0; q < 8; q++) s += Ws[c*27 + ic[q]] * wc[q];
            Krot[(c * G_ + g) * 27 + v] = s;
        }
    } else {
        if (t < 320) g_acc[t] = 0.f;
    }
}

// merged K-matrix build
#define NK1 (AO * KG1)
#define NK2 (AO * KG2)
__global__ void computeK_all(const float* __restrict__ Wg1,
                             const float* __restrict__ Wg2,
                             const float* __restrict__ Wres) {
    int total = 2 * NK1 + NK2;
    int stride = gridDim.x * blockDim.x;
    for (int gi = blockIdx.x * blockDim.x + threadIdx.x; gi < total; gi += stride) {
        const float* Wg; const float* w; __half* dst; int Cin, idx;
        if (gi < NK1)            { Wg = Wg1;  w = g_w;        dst = g_Acmb1;       Cin = CI; idx = gi; }
        else if (gi < NK1 + NK2) { Wg = Wg2;  w = g_w + 1728; dst = g_A2;          Cin = CO; idx = gi - NK1; }
        else                     { Wg = Wres; w = g_w + 3456; dst = g_Acmb1 + NK1; Cin = CI; idx = gi - NK1 - NK2; }
        int cols = Cin * G_;
        int col = idx % cols, row = idx / cols;
        int a = row / G_, o = row % G_;
        int c = col / G_, g = col % G_;
        float s = 0.f;
        #pragma unroll
        for (int r = 0; r < R_; r++)
            s += Wg[(a * Cin + c) * R_ + r] * w[(o * G_ + g) * R_ + r];
        dst[idx] = __float2half_rn(s);
    }
}

// ---------------- conversion/transpose pass ------------------------------------
template <int K, bool NORM, typename Ti>
__global__ void __launch_bounds__(256) convT_kernel(const Ti* __restrict__ src,
                                                    __half* __restrict__ th,
                                                    const float* __restrict__ mu,
                                                    const float* __restrict__ rs) {
    __shared__ float tile[32][33];
    int b = blockIdx.z, k0 = blockIdx.y * 32, n0 = blockIdx.x * 32;
    int tx = threadIdx.x, ty = threadIdx.y;   // 32 x 8
    #pragma unroll
    for (int i = 0; i < 4; i++) {
        int k = ty + i * 8;
        float v = (float)src[((size_t)(b * K + k0 + k)) * V_ + n0 + tx];
        if (NORM) {
            int c = (k0 + k) / G_;
            float m_ = mu[b * CO + c], r_ = rs[b * CO + c];
            v = fmaxf((v - m_) * r_, 0.f);
        }
        tile[k][tx] = v;
    }
    __syncthreads();
    int tid = ty * 32 + tx;
    #pragma unroll
    for (int i = 0; i < 2; i++) {
        int e = tid + i * 256;
        int n = e >> 4, w = e & 15;
        __half2 hh;
        hh.x = __float2half_rn(tile[2 * w][n]);
        hh.y = __float2half_rn(tile[2 * w + 1][n]);
        size_t base = ((size_t)b * V_ + n0 + n) * K + k0 + 2 * w;
        *(__half2*)(th + base) = hh;
    }
}

// ---------------- mma.sync fp16 GEMM, cp.async 3-stage pipeline ----------------
#define GST   3
#define GBUF  32768
#define GSMEM (GST * GBUF)
template <int K>
__global__ void __launch_bounds__(256) gemm_h(
    const __half* __restrict__ A, const __half* __restrict__ B,
    __half* __restrict__ C0, __half* __restrict__ C1) {
    extern __shared__ char smem[];
    uint32_t sbase = smem_u32(smem);

    int tid = threadIdx.x;
    int lane = tid & 31, warp = tid >> 5;
    int wm = warp >> 2;          // 0..1
    int wn = warp & 3;           // 0..3
    int b  = blockIdx.z;
    int m0 = blockIdx.y * 128;
    int n0 = blockIdx.x * 128;

    const __half* Bb = B + (size_t)b * V_ * K;
    const int NT = K / 64;

    float acc[4][4][4];
    #pragma unroll
    for (int i = 0; i < 4; i++)
        #pragma unroll
        for (int j = 0; j < 4; j++)
            #pragma unroll
            for (int q = 0; q < 4; q++) acc[i][j][q] = 0.f;

    int lr = tid >> 3, lc = tid & 7;
    uint32_t loff = lr * 128 + ((lc ^ (lr & 7)) << 4);

    auto ldgsts = [&](int ch, int buf) {
        const __half* Ap = A  + ch * 64;
        const __half* Bp = Bb + ch * 64;
        uint32_t base = sbase + buf * GBUF;
        #pragma unroll
        for (int i = 0; i < 4; i++) {
            int r = lr + i * 32;
            uint32_t off = loff + i * 32 * 128;
            CP_ASYNC16(base + off,         Ap + (size_t)(m0 + r) * K + lc * 8);
            CP_ASYNC16(base + 16384 + off, Bp + (size_t)(n0 + r) * K + lc * 8);
        }
    };

    ldgsts(0, 0); CP_COMMIT();
    ldgsts(1, 1); CP_COMMIT();

    for (int it = 0; it < NT; it++) {
        CP_WAIT1();
        __syncthreads();
        if (it + 2 < NT) ldgsts(it + 2, (it + 2) % GST);
        CP_COMMIT();

        uint32_t aBuf = sbase + (it % GST) * GBUF;
        uint32_t bBuf = aBuf + 16384;
        int quad = lane >> 3, l8 = lane & 7;
        #pragma unroll
        for (int kk = 0; kk < 4; kk++) {
            uint32_t af[4][4];
            #pragma unroll
            for (int mt = 0; mt < 4; mt++) {
                int row = wm * 64 + mt * 16 + (lane & 7) + ((lane >> 3) & 1) * 8;
                int cc  = kk * 2 + (lane >> 4);
                uint32_t addr = aBuf + row * 128 + ((cc ^ (row & 7)) << 4);
                LDMATRIX_X4(af[mt][0], af[mt][1], af[mt][2], af[mt][3], addr);
            }
            uint32_t bf[4][2];
            #pragma unroll
            for (int ntp = 0; ntp < 4; ntp += 2) {
                int n = wn * 32 + (ntp + (quad >> 1)) * 8 + l8;
                int cc = kk * 2 + (quad & 1);
                uint32_t addr = bBuf + n * 128 + ((cc ^ (n & 7)) << 4);
                LDMATRIX_X4(bf[ntp][0], bf[ntp][1], bf[ntp + 1][0], bf[ntp + 1][1], addr);
            }
            #pragma unroll
            for (int mt = 0; mt < 4; mt++)
                #pragma unroll
                for (int nt = 0; nt < 4; nt++)
                    MMA_F16(acc[mt][nt][0], acc[mt][nt][1], acc[mt][nt][2], acc[mt][nt][3],
                            af[mt][0], af[mt][1], af[mt][2], af[mt][3],
                            bf[nt][0], bf[nt][1]);
        }
        __syncthreads();
    }

    // epilogue: fp16 stores
    __half* Cb;
    int mloc;
    if (m0 < AO) { Cb = C0 + (size_t)b * AO * V_; mloc = m0; }
    else         { Cb = C1 + (size_t)b * AO * V_; mloc = m0 - AO; }
    int g = lane >> 2, q = lane & 3;
    int mBase = mloc + wm * 64;
    int nBase = n0 + wn * 32;
    #pragma unroll
    for (int mt = 0; mt < 4; mt++) {
        #pragma unroll
        for (int nt = 0; nt < 4; nt++) {
            int row = mBase + mt * 16 + g;
            int col = nBase + nt * 8 + 2 * q;
            __half2 h0 = __floats2half2_rn(acc[mt][nt][0], acc[mt][nt][1]);
            __half2 h1 = __floats2half2_rn(acc[mt][nt][2], acc[mt][nt][3]);
            *(__half2*)(Cb + (size_t)row * V_ + col)       = h0;
            *(__half2*)(Cb + (size_t)(row + 8) * V_ + col) = h1;
        }
    }
}

// ---------------- depthwise conv (8 planes/CTA, vectorized fp16 I/O) ----------
__global__ void __launch_bounds__(256) dwconv_kernel(const __half* __restrict__ src,
                                                     const float* __restrict__ Krot,
                                                     __half* __restrict__ dst,
                                                     float* __restrict__ accSum,
                                                     float* __restrict__ accSq) {
    int dg = blockIdx.x;     // 0..3 (8 planes each)
    int ch = blockIdx.y;     // 0..383
    int b  = blockIdx.z;
    const __half* zin  = src + ((size_t)(b * AO + ch)) * V_;
    __half*       zout = dst + ((size_t)(b * AO + ch)) * V_;

    __shared__ float tile[10][34][34];
    __shared__ float kr[27];
    __shared__ float red[256];

    int tid = threadIdx.x;
    if (tid < 27) kr[tid] = Krot[ch * 27 + tid];

    int z0 = dg * 8;
    // zero borders only: per plane rows 0/33 (34 each) + cols 0/33 of rows 1..32 (64)
    for (int e = tid; e < 10 * 132; e += 256) {
        int p = e / 132, i = e % 132;
        if (i < 34)       tile[p][0][i] = 0.f;
        else if (i < 68)  tile[p][33][i - 34] = 0.f;
        else if (i < 100) tile[p][i - 68 + 1][0] = 0.f;
        else              tile[p][i - 100 + 1][33] = 0.f;
    }
    // vectorized interior: 10 planes x 32 rows x 4 uint4 (8 halves each)
    for (int e = tid; e < 1280; e += 256) {
        int p  = e >> 7;
        int idx = e & 127;
        int h  = idx >> 2, w4 = idx & 3;
        int zp = z0 - 1 + p;
        float* drow = &tile[p][h + 1][w4 * 8 + 1];
        if (zp >= 0 && zp < 32) {
            uint4 v = *(const uint4*)(zin + zp * 1024 + h * 32 + w4 * 8);
            const __half2* hp = (const __half2*)&v;
            #pragma unroll
            for (int q = 0; q < 4; q++) {
                float2 f = __half22float2(hp[q]);
                drow[2 * q]     = f.x;
                drow[2 * q + 1] = f.y;
            }
        } else {
            #pragma unroll
            for (int q = 0; q < 8; q++) drow[q] = 0.f;
        }
    }
    __syncthreads();

    float krr[27];
    #pragma unroll
    for (int m = 0; m < 27; m++) krr[m] = kr[m];

    float lsum = 0.f, lsq = 0.f;
    int tx = tid & 31, ty = tid >> 5;   // 32 x 8
    #pragma unroll
    for (int od = 0; od < 8; od++) {
        for (int hh = ty; hh < 32; hh += 8) {
            float a = 0.f;
            #pragma unroll
            for (int p = 0; p < 3; p++)
                #pragma unroll
                for (int i = 0; i < 3; i++)
                    #pragma unroll
                    for (int j = 0; j < 3; j++)
                        a += tile[od + p][hh + i][tx + j] * krr[p * 9 + i * 3 + j];
            zout[(z0 + od) * 1024 + hh * 32 + tx] = __float2half_rn(a);
            lsum += a;
            lsq  += a * a;
        }
    }
    red[tid] = lsum; __syncthreads();
    for (int s = 128; s > 0; s >>= 1) { if (tid < s) red[tid] += red[tid + s]; __syncthreads(); }
    float bs = red[0]; __syncthreads();
    red[tid] = lsq; __syncthreads();
    for (int s = 128; s > 0; s >>= 1) { if (tid < s) red[tid] += red[tid + s]; __syncthreads(); }
    if (tid == 0) {
        int idx = b * CO + ch / G_;
        atomicAdd(&accSum[idx], bs);
        atomicAdd(&accSq[idx],  red[0]);
    }
}

__global__ void finstat_kernel(const float* __restrict__ sum, const float* __restrict__ sq,
                               float cnt, int n, float* __restrict__ mu, float* __restrict__ rs) {
    int t = threadIdx.x;
    if (t < n) {
        float m = sum[t] / cnt;
        float v = sq[t] / cnt - m * m;
        mu[t] = m;
        rs[t] = rsqrtf(v + 1e-5f);
    }
}

// batchnorm stats of t = relu(instnorm(y2)) + res  (no materialization)
__global__ void __launch_bounds__(256) combine_kernel() {
    int br  = blockIdx.x;
    int b   = br / AO;
    int row = br % AO;
    int a   = row / G_;
    float mu = g_mu2[b * CO + a], rs = g_rs2[b * CO + a];
    const __half2* y2 = (const __half2*)(g_yh   + (size_t)br * V_);
    const __half2* rv = (const __half2*)(g_resh + (size_t)br * V_);
    __shared__ float red[256];
    int tid = threadIdx.x;
    int base2 = blockIdx.y * 1024 + tid * 4;
    float lsum = 0.f, lsq = 0.f;
    #pragma unroll
    for (int q = 0; q < 4; q++) {
        int i2 = base2 + q;
        float2 yv = __half22float2(y2[i2]);
        float2 rr = __half22float2(rv[i2]);
        float ox = fmaxf((yv.x - mu) * rs, 0.f) + rr.x;
        float oy = fmaxf((yv.y - mu) * rs, 0.f) + rr.y;
        lsum += ox + oy;
        lsq  += ox * ox + oy * oy;
    }
    red[tid] = lsum; __syncthreads();
    for (int s = 128; s > 0; s >>= 1) { if (tid < s) red[tid] += red[tid + s]; __syncthreads(); }
    float bs = red[0]; __syncthreads();
    red[tid] = lsq; __syncthreads();
    for (int s = 128; s > 0; s >>= 1) { if (tid < s) red[tid] += red[tid + s]; __syncthreads(); }
    if (tid == 0) {
        atomicAdd(&g_acc[256 + a], bs);
        atomicAdd(&g_acc[288 + a], red[0]);
    }
}

// out = batchnorm(relu(instnorm(y2)) + res), recomputed from fp16 sources
__global__ void __launch_bounds__(256) final_kernel(float* __restrict__ out,
                                                    const float* __restrict__ gamma,
                                                    const float* __restrict__ beta) {
    int i4 = blockIdx.x * 256 + threadIdx.x;    // 0..6291455 (4 elems each)
    int row = i4 >> 13;
    int b = row / AO;
    int a = (row % AO) / G_;
    float mu = g_mu2[b * CO + a], rs = g_rs2[b * CO + a];
    float bmu = g_bmu[a];
    float sc = g_brs[a] * gamma[a];
    float bt = beta[a];
    const __half2* y2 = (const __half2*)g_yh;
    const __half2* rv = (const __half2*)g_resh;
    int i2 = i4 * 2;
    float2 ya = __half22float2(y2[i2]),     yb = __half22float2(y2[i2 + 1]);
    float2 ra = __half22float2(rv[i2]),     rb = __half22float2(rv[i2 + 1]);
    float4 o;
    o.x = (fmaxf((ya.x - mu) * rs, 0.f) + ra.x - bmu) * sc + bt;
    o.y = (fmaxf((ya.y - mu) * rs, 0.f) + ra.y - bmu) * sc + bt;
    o.z = (fmaxf((yb.x - mu) * rs, 0.f) + rb.x - bmu) * sc + bt;
    o.w = (fmaxf((yb.y - mu) * rs, 0.f) + rb.y - bmu) * sc + bt;
    ((float4*)out)[i4] = o;
}

// ---------------- launch ------------------------------------------------------
extern "C" void kernel_launch(void* const* d_in, const int* in_sizes, int n_in,
                              void* d_out, int out_size) {
    const float* x      = (const float*)d_in[0];
    const float* H      = (const float*)d_in[1];
    const float* Href1  = (const float*)d_in[2];
    const float* Href2  = (const float*)d_in[3];
    const float* Hrefr  = (const float*)d_in[4];
    const float* Wg1    = (const float*)d_in[5];
    const float* Ws1    = (const float*)d_in[6];
    const float* Wg2    = (const float*)d_in[7];
    const float* Ws2    = (const float*)d_in[8];
    const float* Wres   = (const float*)d_in[9];
    const float* gamma  = (const float*)d_in[10];
    const float* beta   = (const float*)d_in[11];
    float* out = (float*)d_out;

    float *Krot1, *Krot2, *acc, *mu1, *rs1, *mu2, *rs2, *bmu, *brs;
    __half *Acmb1, *A2, *xt, *yt, *zh, *resh, *yh;
    cudaGetSymbolAddress((void**)&Acmb1, g_Acmb1);
    cudaGetSymbolAddress((void**)&A2,    g_A2);
    cudaGetSymbolAddress((void**)&xt,    g_xt);
    cudaGetSymbolAddress((void**)&yt,    g_yt);
    cudaGetSymbolAddress((void**)&zh,    g_zh);
    cudaGetSymbolAddress((void**)&resh,  g_resh);
    cudaGetSymbolAddress((void**)&yh,    g_yh);
    cudaGetSymbolAddress((void**)&Krot1, g_Krot1);
    cudaGetSymbolAddress((void**)&Krot2, g_Krot2);
    cudaGetSymbolAddress((void**)&acc,   g_acc);
    cudaGetSymbolAddress((void**)&mu1,   g_mu1);
    cudaGetSymbolAddress((void**)&rs1,   g_rs1);
    cudaGetSymbolAddress((void**)&mu2,   g_mu2);
    cudaGetSymbolAddress((void**)&rs2,   g_rs2);
    cudaGetSymbolAddress((void**)&bmu,   g_bmu);
    cudaGetSymbolAddress((void**)&brs,   g_brs);

    cudaFuncSetAttribute(gemm_h<KG1>, cudaFuncAttributeMaxDynamicSharedMemorySize, GSMEM);
    cudaFuncSetAttribute(gemm_h<KG2>, cudaFuncAttributeMaxDynamicSharedMemorySize, GSMEM);

    setup_kernel<<<6, 352>>>(H, Href1, Href2, Hrefr, Ws1, Ws2);
    computeK_all<<<1152, 256>>>(Wg1, Wg2, Wres);

    // x -> fp16 transposed [b][v][k]
    convT_kernel<KG1, false, float><<<dim3(1024, 6, 2), dim3(32, 8)>>>(x, xt, nullptr, nullptr);

    // fused: [z1 ; res] = [K1 ; Kres] @ x   (M = 768)
    gemm_h<KG1><<<dim3(256, 6, 2), 256, GSMEM>>>(Acmb1, xt, zh, resh);
    // y1 = dwconv(z1) + stats
    dwconv_kernel<<<dim3(4, 384, 2), 256>>>(zh, Krot1, yh, acc + 0, acc + 64);
    finstat_kernel<<<1, 64>>>(acc + 0, acc + 64, (float)(G_ * V_), 64, mu1, rs1);
    // relu(instnorm(y1)) -> fp16 transposed
    convT_kernel<KG2, true, __half><<<dim3(1024, 12, 2), dim3(32, 8)>>>(yh, yt, mu1, rs1);
    // z2 = K2 @ (.)
    gemm_h<KG2><<<dim3(256, 3, 2), 256, GSMEM>>>(A2, yt, zh, zh);
    // y2 = dwconv(z2) + stats
    dwconv_kernel<<<dim3(4, 384, 2), 256>>>(zh, Krot2, yh, acc + 128, acc + 192);
    finstat_kernel<<<1, 64>>>(acc + 128, acc + 192, (float)(G_ * V_), 64, mu2, rs2);
    // batchnorm stats of t (no materialization)
    combine_kernel<<<dim3(768, 16), 256>>>();
    finstat_kernel<<<1, 32>>>(acc + 256, acc + 288, (float)(B_ * G_ * V_), 32, bmu, brs);
    // out = batchnorm(relu(instnorm(y2)) + res)
    final_kernel<<<24576, 256>>>(out, gamma, beta);
    cudaMemcpyAsync(out + NY, H, 108 * sizeof(float), cudaMemcpyDeviceToDevice);
}